// round 2
// baseline (speedup 1.0000x reference)
#include <cuda_runtime.h>
#include <math.h>

#define BB 32
#define SS 512
#define DD 512
#define HH 8
#define DHH 64
#define TT (BB*SS)   // 16384 tokens

// ---- scratch (__device__ globals are allowed; no dynamic alloc) ----
__device__ float g_h[(size_t)TT * DD];                 // LN output
__device__ float g_q[(size_t)BB * HH * SS * DHH];      // [b,h,s,d]
__device__ float g_k[(size_t)BB * HH * SS * DHH];
__device__ float g_v[(size_t)BB * HH * SS * DHH];

// output layout: [ ctx0: B*D ][ ctx: B*S*D ][ probs: B*H*S*S ]
#define OUT_CTX   ((size_t)BB * DD)
#define OUT_PROBS (OUT_CTX + (size_t)BB * SS * DD)

// ============================================================
// Kernel 1: embedding + positional + LayerNorm (float4 path)
// 128 threads, one block per token row
// ============================================================
__global__ void embed_ln_kernel(const int* __restrict__ x_seq,
                                const float* __restrict__ word_emb,
                                const float* __restrict__ pos_emb,
                                const float* __restrict__ ln_w,
                                const float* __restrict__ ln_b) {
    int row = blockIdx.x;
    int s   = row & (SS - 1);
    int tid = threadIdx.x;       // 128
    int x   = x_seq[row];
    const float4* we = (const float4*)(word_emb + (size_t)x * DD);
    const float4* pe = (const float4*)(pos_emb  + (size_t)s * DD);

    float4 w4 = we[tid], p4 = pe[tid];
    float4 v4 = make_float4(w4.x + p4.x, w4.y + p4.y, w4.z + p4.z, w4.w + p4.w);
    float sum = v4.x + v4.y + v4.z + v4.w;

    __shared__ float red[4];
#pragma unroll
    for (int o = 16; o > 0; o >>= 1) sum += __shfl_xor_sync(~0u, sum, o);
    if ((tid & 31) == 0) red[tid >> 5] = sum;
    __syncthreads();
    float mu = (red[0] + red[1] + red[2] + red[3]) * (1.0f / DD);
    __syncthreads();

    float dx = v4.x - mu, dy = v4.y - mu, dz = v4.z - mu, dw = v4.w - mu;
    float sq = dx * dx + dy * dy + dz * dz + dw * dw;
#pragma unroll
    for (int o = 16; o > 0; o >>= 1) sq += __shfl_xor_sync(~0u, sq, o);
    if ((tid & 31) == 0) red[tid >> 5] = sq;
    __syncthreads();
    float var = (red[0] + red[1] + red[2] + red[3]) * (1.0f / DD);
    float rstd = rsqrtf(var + 1e-5f);

    float4 lw = ((const float4*)ln_w)[tid];
    float4 lb = ((const float4*)ln_b)[tid];
    float4 o4;
    o4.x = dx * rstd * lw.x + lb.x;
    o4.y = dy * rstd * lw.y + lb.y;
    o4.z = dz * rstd * lw.z + lb.z;
    o4.w = dw * rstd * lw.w + lb.w;
    ((float4*)(g_h + (size_t)row * DD))[tid] = o4;
}

// ============================================================
// Kernel 2: QKV projection  C = h @ W^T + b
// 64x64 tile, k-chunk 32, transposed smem tiles -> LDS.128 operands
// grid (T/64, D/64, 3), 256 threads, 4x4 microtile
// ============================================================
__global__ void __launch_bounds__(256) qkv_gemm_kernel(
        const float* __restrict__ wq, const float* __restrict__ bq,
        const float* __restrict__ wk, const float* __restrict__ bk,
        const float* __restrict__ wv, const float* __restrict__ bv) {
    const float* W; const float* bias; float* out;
    int z = blockIdx.z;
    if      (z == 0) { W = wq; bias = bq; out = g_q; }
    else if (z == 1) { W = wk; bias = bk; out = g_k; }
    else             { W = wv; bias = bv; out = g_v; }

    // transposed tiles: [kk][row], stride 68 (16B-aligned, conflict-spread)
    __shared__ float Ast[32 * 68];
    __shared__ float Bst[32 * 68];

    int row0 = blockIdx.x * 64;
    int col0 = blockIdx.y * 64;
    int tid = threadIdx.x;
    int tx = tid & 15, ty = tid >> 4;

    float acc[4][4] = {};

    for (int k0 = 0; k0 < DD; k0 += 32) {
        // 64 rows x 32 cols = 512 float4 loads; 256 threads x 2
#pragma unroll
        for (int t = 0; t < 2; t++) {
            int idx = tid + t * 256;
            int r = idx >> 3;             // 0..63
            int c4 = (idx & 7) * 4;       // 0..28
            float4 a = *(const float4*)&g_h[(size_t)(row0 + r) * DD + k0 + c4];
            Ast[(c4 + 0) * 68 + r] = a.x;
            Ast[(c4 + 1) * 68 + r] = a.y;
            Ast[(c4 + 2) * 68 + r] = a.z;
            Ast[(c4 + 3) * 68 + r] = a.w;
            float4 b = *(const float4*)&W[(size_t)(col0 + r) * DD + k0 + c4];
            Bst[(c4 + 0) * 68 + r] = b.x;
            Bst[(c4 + 1) * 68 + r] = b.y;
            Bst[(c4 + 2) * 68 + r] = b.z;
            Bst[(c4 + 3) * 68 + r] = b.w;
        }
        __syncthreads();
#pragma unroll
        for (int kk = 0; kk < 32; kk++) {
            float4 a4 = *(const float4*)&Ast[kk * 68 + ty * 4];
            float4 b4 = *(const float4*)&Bst[kk * 68 + tx * 4];
            float a[4] = {a4.x, a4.y, a4.z, a4.w};
            float b[4] = {b4.x, b4.y, b4.z, b4.w};
#pragma unroll
            for (int i = 0; i < 4; i++)
#pragma unroll
                for (int j = 0; j < 4; j++) acc[i][j] = fmaf(a[i], b[j], acc[i][j]);
        }
        __syncthreads();
    }

    int colb = col0 + tx * 4;
    int h_ = colb >> 6, d_ = colb & 63;
    float4 bia = *(const float4*)&bias[colb];
#pragma unroll
    for (int i = 0; i < 4; i++) {
        int t  = row0 + ty * 4 + i;
        int b_ = t >> 9, s_ = t & 511;
        float4 o4 = make_float4(acc[i][0] + bia.x, acc[i][1] + bia.y,
                                acc[i][2] + bia.z, acc[i][3] + bia.w);
        *(float4*)&out[((((size_t)b_ * HH + h_) * SS) + s_) * DHH + d_] = o4;
    }
}

// ============================================================
// Kernel 3: attention. One CTA per (q-tile 64, head, batch), 256 thr
// smem: sc 64x516 | qst 64x68 (dh-major) | kvt 64x68 | msm 512 | rinv 64
// ============================================================
#define SCP 516
#define ATTN_SMEM ((64*SCP + 2*64*68 + 512 + 64) * sizeof(float))

__global__ void __launch_bounds__(256) attn_kernel(const int* __restrict__ mask,
                                                   float* __restrict__ out) {
    int qt = blockIdx.x, hh = blockIdx.y, bb = blockIdx.z;
    extern __shared__ float sm[];
    float* sc   = sm;                      // 64*516 scores/probs
    float* qst  = sc + 64 * SCP;           // [dh][qrow] stride 68
    float* kvt  = qst + 64 * 68;           // K: [dh][srow]; V: [srow][dh]
    float* msm  = kvt + 64 * 68;           // 512 mask factors
    float* rinv = msm + 512;               // 64

    int tid = threadIdx.x;                 // 256
    int tx = tid & 15, ty = tid >> 4;
    size_t bh = (size_t)bb * HH + hh;
    const float* qptr = g_q + (bh * SS + (size_t)qt * 64) * DHH;
    const float* kptr = g_k + bh * SS * DHH;
    const float* vptr = g_v + bh * SS * DHH;

    // load q tile transposed: [dh][row]
#pragma unroll
    for (int t = 0; t < 4; t++) {
        int idx = tid + t * 256;
        int r = idx >> 4;                  // 0..63 (q row)
        int c4 = (idx & 15) * 4;           // dh
        float4 a = *(const float4*)&qptr[(size_t)r * 64 + c4];
        qst[(c4 + 0) * 68 + r] = a.x;
        qst[(c4 + 1) * 68 + r] = a.y;
        qst[(c4 + 2) * 68 + r] = a.z;
        qst[(c4 + 3) * 68 + r] = a.w;
    }
    for (int i = tid; i < SS; i += 256)
        msm[i] = (1.0f - (float)mask[(size_t)bb * SS + i]) * -10000.0f;
    __syncthreads();

    // ---- scores = (q k^T)/8 * m ----
    for (int kt = 0; kt < 8; kt++) {
#pragma unroll
        for (int t = 0; t < 4; t++) {
            int idx = tid + t * 256;
            int r = idx >> 4;
            int c4 = (idx & 15) * 4;
            float4 a = *(const float4*)&kptr[(size_t)(kt * 64 + r) * 64 + c4];
            kvt[(c4 + 0) * 68 + r] = a.x;
            kvt[(c4 + 1) * 68 + r] = a.y;
            kvt[(c4 + 2) * 68 + r] = a.z;
            kvt[(c4 + 3) * 68 + r] = a.w;
        }
        __syncthreads();
        float acc[4][4] = {};
#pragma unroll 16
        for (int kk = 0; kk < 64; kk++) {
            float4 a4 = *(const float4*)&qst[kk * 68 + ty * 4];
            float4 b4 = *(const float4*)&kvt[kk * 68 + tx * 4];
            float a[4] = {a4.x, a4.y, a4.z, a4.w};
            float b[4] = {b4.x, b4.y, b4.z, b4.w};
#pragma unroll
            for (int i = 0; i < 4; i++)
#pragma unroll
                for (int j = 0; j < 4; j++) acc[i][j] = fmaf(a[i], b[j], acc[i][j]);
        }
        int c = kt * 64 + tx * 4;
        float4 m4 = *(const float4*)&msm[c];
#pragma unroll
        for (int i = 0; i < 4; i++) {
            float4 s4 = make_float4(acc[i][0] * 0.125f * m4.x, acc[i][1] * 0.125f * m4.y,
                                    acc[i][2] * 0.125f * m4.z, acc[i][3] * 0.125f * m4.w);
            *(float4*)&sc[(ty * 4 + i) * SCP + c] = s4;
        }
        __syncthreads();
    }

    // ---- softmax: keep unnormalized exps in sc, save 1/sum ----
    {
        int r = tid >> 2, l4 = tid & 3;    // 4 lanes per row
        float mx = -INFINITY;
        for (int c = l4 * 4; c < SS; c += 16) {
            float4 s4 = *(const float4*)&sc[r * SCP + c];
            mx = fmaxf(mx, fmaxf(fmaxf(s4.x, s4.y), fmaxf(s4.z, s4.w)));
        }
        mx = fmaxf(mx, __shfl_xor_sync(~0u, mx, 1));
        mx = fmaxf(mx, __shfl_xor_sync(~0u, mx, 2));
        float sum = 0.f;
        for (int c = l4 * 4; c < SS; c += 16) {
            float4 s4 = *(const float4*)&sc[r * SCP + c];
            s4.x = __expf(s4.x - mx); s4.y = __expf(s4.y - mx);
            s4.z = __expf(s4.z - mx); s4.w = __expf(s4.w - mx);
            *(float4*)&sc[r * SCP + c] = s4;
            sum += s4.x + s4.y + s4.z + s4.w;
        }
        sum += __shfl_xor_sync(~0u, sum, 1);
        sum += __shfl_xor_sync(~0u, sum, 2);
        if (l4 == 0) rinv[r] = 1.0f / sum;
    }
    __syncthreads();

    // ---- write probs (normalized, float4) ----
    {
        float* pbase = out + OUT_PROBS + (bh * SS + (size_t)qt * 64) * SS;
#pragma unroll
        for (int t = 0; t < 32; t++) {
            int idx = tid + t * 256;       // 8192 float4
            int r = idx >> 7, c = (idx & 127) * 4;
            float rv = rinv[r];
            float4 e4 = *(const float4*)&sc[r * SCP + c];
            float4 p4 = make_float4(e4.x * rv, e4.y * rv, e4.z * rv, e4.w * rv);
            *(float4*)&pbase[(size_t)r * SS + c] = p4;
        }
    }

    // ---- ctx = probs @ v ----
    float acc2[4][4] = {};
    for (int kt = 0; kt < 8; kt++) {
        __syncthreads();
#pragma unroll
        for (int t = 0; t < 4; t++) {
            int idx = tid + t * 256;
            int r = idx >> 4;              // s row within tile
            int c4 = (idx & 15) * 4;       // dh
            float4 a = *(const float4*)&vptr[(size_t)(kt * 64 + r) * 64 + c4];
            *(float4*)&kvt[r * 68 + c4] = a;   // natural layout
        }
        __syncthreads();
#pragma unroll 16
        for (int kk = 0; kk < 64; kk++) {
            float4 b4 = *(const float4*)&kvt[kk * 68 + tx * 4];
            float b[4] = {b4.x, b4.y, b4.z, b4.w};
            float a[4];
#pragma unroll
            for (int i = 0; i < 4; i++) a[i] = sc[(ty * 4 + i) * SCP + kt * 64 + kk];
#pragma unroll
            for (int i = 0; i < 4; i++)
#pragma unroll
                for (int j = 0; j < 4; j++) acc2[i][j] = fmaf(a[i], b[j], acc2[i][j]);
        }
    }

    // ---- write ctx (and ctx[:,0,:]) ----
    int cc = hh * 64 + tx * 4;
#pragma unroll
    for (int i = 0; i < 4; i++) {
        int r = ty * 4 + i;
        int q = qt * 64 + r;
        float rv = rinv[r];
        float4 o4 = make_float4(acc2[i][0] * rv, acc2[i][1] * rv,
                                acc2[i][2] * rv, acc2[i][3] * rv);
        *(float4*)&out[OUT_CTX + ((size_t)bb * SS + q) * DD + cc] = o4;
        if (q == 0) *(float4*)&out[(size_t)bb * DD + cc] = o4;
    }
}

// ============================================================
extern "C" void kernel_launch(void* const* d_in, const int* in_sizes, int n_in,
                              void* d_out, int out_size) {
    const int*   x_seq    = (const int*)  d_in[0];
    const int*   mask     = (const int*)  d_in[1];
    const float* word_emb = (const float*)d_in[2];
    const float* pos_emb  = (const float*)d_in[3];
    const float* ln_w     = (const float*)d_in[4];
    const float* ln_b     = (const float*)d_in[5];
    const float* wq       = (const float*)d_in[6];
    const float* bq       = (const float*)d_in[7];
    const float* wk       = (const float*)d_in[8];
    const float* bk       = (const float*)d_in[9];
    const float* wv       = (const float*)d_in[10];
    const float* bv       = (const float*)d_in[11];
    float* out = (float*)d_out;

    embed_ln_kernel<<<TT, 128>>>(x_seq, word_emb, pos_emb, ln_w, ln_b);

    dim3 ggrid(TT / 64, DD / 64, 3);
    qkv_gemm_kernel<<<ggrid, 256>>>(wq, bq, wk, bk, wv, bv);

    cudaFuncSetAttribute(attn_kernel, cudaFuncAttributeMaxDynamicSharedMemorySize,
                         (int)ATTN_SMEM);
    dim3 agrid(SS / 64, HH, BB);
    attn_kernel<<<agrid, 256, ATTN_SMEM>>>(mask, out);
}

// round 3
// speedup vs baseline: 1.2334x; 1.2334x over previous
#include <cuda_runtime.h>
#include <math.h>

#define BB 32
#define SS 512
#define DD 512
#define HH 8
#define DHH 64
#define TT (BB*SS)   // 16384 tokens

// ---- scratch (__device__ globals are allowed; no dynamic alloc) ----
__device__ float g_h[(size_t)TT * DD];                 // LN output
__device__ float g_q[(size_t)BB * HH * SS * DHH];      // [b,h,s,d]
__device__ float g_k[(size_t)BB * HH * SS * DHH];
__device__ float g_v[(size_t)BB * HH * SS * DHH];

// output layout: [ ctx0: B*D ][ ctx: B*S*D ][ probs: B*H*S*S ]
#define OUT_CTX   ((size_t)BB * DD)
#define OUT_PROBS (OUT_CTX + (size_t)BB * SS * DD)

// ============================================================
// Kernel 1: embedding + positional + LayerNorm (float4 path)
// ============================================================
__global__ void embed_ln_kernel(const int* __restrict__ x_seq,
                                const float* __restrict__ word_emb,
                                const float* __restrict__ pos_emb,
                                const float* __restrict__ ln_w,
                                const float* __restrict__ ln_b) {
    int row = blockIdx.x;
    int s   = row & (SS - 1);
    int tid = threadIdx.x;       // 128
    int x   = x_seq[row];
    const float4* we = (const float4*)(word_emb + (size_t)x * DD);
    const float4* pe = (const float4*)(pos_emb  + (size_t)s * DD);

    float4 w4 = we[tid], p4 = pe[tid];
    float4 v4 = make_float4(w4.x + p4.x, w4.y + p4.y, w4.z + p4.z, w4.w + p4.w);
    float sum = v4.x + v4.y + v4.z + v4.w;

    __shared__ float red[4];
#pragma unroll
    for (int o = 16; o > 0; o >>= 1) sum += __shfl_xor_sync(~0u, sum, o);
    if ((tid & 31) == 0) red[tid >> 5] = sum;
    __syncthreads();
    float mu = (red[0] + red[1] + red[2] + red[3]) * (1.0f / DD);
    __syncthreads();

    float dx = v4.x - mu, dy = v4.y - mu, dz = v4.z - mu, dw = v4.w - mu;
    float sq = dx * dx + dy * dy + dz * dz + dw * dw;
#pragma unroll
    for (int o = 16; o > 0; o >>= 1) sq += __shfl_xor_sync(~0u, sq, o);
    if ((tid & 31) == 0) red[tid >> 5] = sq;
    __syncthreads();
    float var = (red[0] + red[1] + red[2] + red[3]) * (1.0f / DD);
    float rstd = rsqrtf(var + 1e-5f);

    float4 lw = ((const float4*)ln_w)[tid];
    float4 lb = ((const float4*)ln_b)[tid];
    float4 o4;
    o4.x = dx * rstd * lw.x + lb.x;
    o4.y = dy * rstd * lw.y + lb.y;
    o4.z = dz * rstd * lw.z + lb.z;
    o4.w = dw * rstd * lw.w + lb.w;
    ((float4*)(g_h + (size_t)row * DD))[tid] = o4;
}

// ============================================================
// Kernel 2: QKV projection  C = h @ W^T + b
// 128x128 CTA tile, k-chunk 16, 8 warps (4x2), warp tile 32x64,
// 8x8 microtile, lane map ar=lane%4 (rows), bc=lane/4 (cols)
// ============================================================
#define GSTR 132   // smem tile stride [k][row]

__global__ void __launch_bounds__(256, 2) qkv_gemm_kernel(
        const float* __restrict__ wq, const float* __restrict__ bq,
        const float* __restrict__ wk, const float* __restrict__ bk,
        const float* __restrict__ wv, const float* __restrict__ bv) {
    const float* W; const float* bias; float* out;
    int z = blockIdx.z;
    if      (z == 0) { W = wq; bias = bq; out = g_q; }
    else if (z == 1) { W = wk; bias = bk; out = g_k; }
    else             { W = wv; bias = bv; out = g_v; }

    __shared__ float As[16 * GSTR];
    __shared__ float Bs[16 * GSTR];

    int tid  = threadIdx.x;
    int warp = tid >> 5, lane = tid & 31;
    int wr = warp & 3, wc = warp >> 2;       // warp grid 4x2
    int ar = lane & 3, bc = lane >> 2;       // micro lane map
    int row0 = blockIdx.x * 128;
    int col0 = blockIdx.y * 128;

    // load enumeration: t in 0..1 : r = (t*8+warp)*8 + bc, c4 = ar*4
    float4 pa[2], pb[2];
#pragma unroll
    for (int t = 0; t < 2; t++) {
        int r = ((t * 8 + warp) << 3) + bc;
        pa[t] = *(const float4*)&g_h[(size_t)(row0 + r) * DD + ar * 4];
        pb[t] = *(const float4*)&W  [(size_t)(col0 + r) * DD + ar * 4];
    }

    float acc[8][8] = {};

    for (int k0 = 0; k0 < DD; k0 += 16) {
        __syncthreads();
#pragma unroll
        for (int t = 0; t < 2; t++) {
            int r = ((t * 8 + warp) << 3) + bc;
            int c4 = ar * 4;
            As[(c4 + 0) * GSTR + r] = pa[t].x;
            As[(c4 + 1) * GSTR + r] = pa[t].y;
            As[(c4 + 2) * GSTR + r] = pa[t].z;
            As[(c4 + 3) * GSTR + r] = pa[t].w;
            Bs[(c4 + 0) * GSTR + r] = pb[t].x;
            Bs[(c4 + 1) * GSTR + r] = pb[t].y;
            Bs[(c4 + 2) * GSTR + r] = pb[t].z;
            Bs[(c4 + 3) * GSTR + r] = pb[t].w;
        }
        __syncthreads();
        int kn = k0 + 16;
        if (kn < DD) {
#pragma unroll
            for (int t = 0; t < 2; t++) {
                int r = ((t * 8 + warp) << 3) + bc;
                pa[t] = *(const float4*)&g_h[(size_t)(row0 + r) * DD + kn + ar * 4];
                pb[t] = *(const float4*)&W  [(size_t)(col0 + r) * DD + kn + ar * 4];
            }
        }
#pragma unroll
        for (int kk = 0; kk < 16; kk++) {
            float4 a0 = *(const float4*)&As[kk * GSTR + wr * 32 + ar * 8];
            float4 a1 = *(const float4*)&As[kk * GSTR + wr * 32 + ar * 8 + 4];
            float4 b0 = *(const float4*)&Bs[kk * GSTR + wc * 64 + bc * 8];
            float4 b1 = *(const float4*)&Bs[kk * GSTR + wc * 64 + bc * 8 + 4];
            float a[8] = {a0.x, a0.y, a0.z, a0.w, a1.x, a1.y, a1.z, a1.w};
            float b[8] = {b0.x, b0.y, b0.z, b0.w, b1.x, b1.y, b1.z, b1.w};
#pragma unroll
            for (int i = 0; i < 8; i++)
#pragma unroll
                for (int j = 0; j < 8; j++) acc[i][j] = fmaf(a[i], b[j], acc[i][j]);
        }
    }

    int colb = col0 + wc * 64 + bc * 8;
    int h_ = colb >> 6, d_ = colb & 63;
    float4 bi0 = *(const float4*)&bias[colb];
    float4 bi1 = *(const float4*)&bias[colb + 4];
#pragma unroll
    for (int i = 0; i < 8; i++) {
        int t  = row0 + wr * 32 + ar * 8 + i;
        int b_ = t >> 9, s_ = t & 511;
        size_t o = ((((size_t)b_ * HH + h_) * SS) + s_) * DHH + d_;
        *(float4*)&out[o]     = make_float4(acc[i][0] + bi0.x, acc[i][1] + bi0.y,
                                            acc[i][2] + bi0.z, acc[i][3] + bi0.w);
        *(float4*)&out[o + 4] = make_float4(acc[i][4] + bi1.x, acc[i][5] + bi1.y,
                                            acc[i][6] + bi1.z, acc[i][7] + bi1.w);
    }
}

// ============================================================
// Kernel 3: attention. CTA = (q-tile 64, head, batch), 256 thr.
// QK^T: 2 k-tiles of 256, warp grid 2x4, 8x8 micro.
// PV: split-k over 4 warp-pairs, 8x8 micro (strided rows), smem reduce.
// ============================================================
#define SCP 516
#define QTS 68
#define KTS 260
#define SC_FLOATS   (64 * SCP)            // 33024
#define QT_FLOATS   (64 * QTS)            // 4352
#define BUF_FLOATS  (256 * 68)            // 17408 (holds kT 64*260=16640 too)
#define ATTN_SMEM ((SC_FLOATS + QT_FLOATS + BUF_FLOATS + 512 + 64) * sizeof(float))

__global__ void __launch_bounds__(256, 1) attn_kernel(const int* __restrict__ mask,
                                                      float* __restrict__ out) {
    int qt = blockIdx.x, hh = blockIdx.y, bb = blockIdx.z;
    extern __shared__ float sm[];
    float* sc   = sm;                       // scores/probs strip 64 x 516
    float* qT   = sc + SC_FLOATS;           // [dh][qrow] stride 68
    float* buf  = qT + QT_FLOATS;           // kT [dh][kcol] s260 / vs [k][d] s68
    float* msm  = buf + BUF_FLOATS;         // 512
    float* rinv = msm + 512;                // 64

    int tid  = threadIdx.x;
    int warp = tid >> 5, lane = tid & 31;
    int ar = lane & 3, bc = lane >> 2;
    size_t bh = (size_t)bb * HH + hh;
    const float* qptr = g_q + (bh * SS + (size_t)qt * 64) * DHH;
    const float* kptr = g_k + bh * SS * DHH;
    const float* vptr = g_v + bh * SS * DHH;

    // ---- phase 0: qT transposed load + mask ----
#pragma unroll
    for (int t = 0; t < 4; t++) {
        int r  = warp * 8 + bc;             // q row 0..63
        int c4 = t * 16 + ar * 4;           // dh
        float4 a = *(const float4*)&qptr[(size_t)r * DHH + c4];
        qT[(c4 + 0) * QTS + r] = a.x;
        qT[(c4 + 1) * QTS + r] = a.y;
        qT[(c4 + 2) * QTS + r] = a.z;
        qT[(c4 + 3) * QTS + r] = a.w;
    }
    for (int i = tid; i < SS; i += 256)
        msm[i] = (1.0f - (float)mask[(size_t)bb * SS + i]) * -10000.0f;

    // ---- phase 1: scores = (q k^T)/8 * m, 2 tiles of 256 cols ----
    int wq = warp >> 2, wk = warp & 3;      // warp grid 2x4 over 64x256
    for (int kt = 0; kt < 2; kt++) {
        __syncthreads();                    // kT/buf free; qT/msm visible
#pragma unroll
        for (int t = 0; t < 16; t++) {
            int rb = (t >> 2) * 8 + warp;   // 0..31
            int r  = rb * 8 + bc;           // k col 0..255
            int c4 = (t & 3) * 16 + ar * 4; // dh
            float4 a = *(const float4*)&kptr[(size_t)(kt * 256 + r) * DHH + c4];
            buf[(c4 + 0) * KTS + r] = a.x;
            buf[(c4 + 1) * KTS + r] = a.y;
            buf[(c4 + 2) * KTS + r] = a.z;
            buf[(c4 + 3) * KTS + r] = a.w;
        }
        __syncthreads();
        float acc[8][8] = {};
#pragma unroll 4
        for (int kk = 0; kk < 64; kk++) {
            float4 a0 = *(const float4*)&qT[kk * QTS + wq * 32 + ar * 8];
            float4 a1 = *(const float4*)&qT[kk * QTS + wq * 32 + ar * 8 + 4];
            float4 b0 = *(const float4*)&buf[kk * KTS + wk * 64 + bc * 8];
            float4 b1 = *(const float4*)&buf[kk * KTS + wk * 64 + bc * 8 + 4];
            float a[8] = {a0.x, a0.y, a0.z, a0.w, a1.x, a1.y, a1.z, a1.w};
            float b[8] = {b0.x, b0.y, b0.z, b0.w, b1.x, b1.y, b1.z, b1.w};
#pragma unroll
            for (int i = 0; i < 8; i++)
#pragma unroll
                for (int j = 0; j < 8; j++) acc[i][j] = fmaf(a[i], b[j], acc[i][j]);
        }
        int col = kt * 256 + wk * 64 + bc * 8;
        float4 m0 = *(const float4*)&msm[col];
        float4 m1 = *(const float4*)&msm[col + 4];
#pragma unroll
        for (int i = 0; i < 8; i++) {
            int q = wq * 32 + ar * 8 + i;
            *(float4*)&sc[q * SCP + col] =
                make_float4(acc[i][0] * 0.125f * m0.x, acc[i][1] * 0.125f * m0.y,
                            acc[i][2] * 0.125f * m0.z, acc[i][3] * 0.125f * m0.w);
            *(float4*)&sc[q * SCP + col + 4] =
                make_float4(acc[i][4] * 0.125f * m1.x, acc[i][5] * 0.125f * m1.y,
                            acc[i][6] * 0.125f * m1.z, acc[i][7] * 0.125f * m1.w);
        }
    }
    __syncthreads();

    // ---- phase 2: softmax (keep unnormalized exps, store 1/sum) ----
    {
        int r = tid >> 2, l4 = tid & 3;
        float mx = -INFINITY;
        for (int c = l4 * 4; c < SS; c += 16) {
            float4 s4 = *(const float4*)&sc[r * SCP + c];
            mx = fmaxf(mx, fmaxf(fmaxf(s4.x, s4.y), fmaxf(s4.z, s4.w)));
        }
        mx = fmaxf(mx, __shfl_xor_sync(~0u, mx, 1));
        mx = fmaxf(mx, __shfl_xor_sync(~0u, mx, 2));
        float sum = 0.f;
        for (int c = l4 * 4; c < SS; c += 16) {
            float4 s4 = *(const float4*)&sc[r * SCP + c];
            s4.x = __expf(s4.x - mx); s4.y = __expf(s4.y - mx);
            s4.z = __expf(s4.z - mx); s4.w = __expf(s4.w - mx);
            *(float4*)&sc[r * SCP + c] = s4;
            sum += s4.x + s4.y + s4.z + s4.w;
        }
        sum += __shfl_xor_sync(~0u, sum, 1);
        sum += __shfl_xor_sync(~0u, sum, 2);
        if (l4 == 0) rinv[r] = 1.0f / sum;
    }
    __syncthreads();

    // ---- phase 3: write probs (normalized) ----
    {
        float* pbase = out + OUT_PROBS + (bh * SS + (size_t)qt * 64) * SS;
#pragma unroll
        for (int t = 0; t < 32; t++) {
            int idx = tid + t * 256;
            int r = idx >> 7, c = (idx & 127) * 4;
            float rv = rinv[r];
            float4 e4 = *(const float4*)&sc[r * SCP + c];
            *(float4*)&pbase[(size_t)r * SS + c] =
                make_float4(e4.x * rv, e4.y * rv, e4.z * rv, e4.w * rv);
        }
    }

    // ---- phase 4: ctx = probs @ v, split-k over 4 warp pairs ----
    int g   = warp >> 1;                    // split-k group 0..3
    int wq2 = warp & 1;                     // q half
    float acc2[8][8] = {};
    for (int st = 0; st < 2; st++) {
        __syncthreads();                    // buf free
#pragma unroll
        for (int t = 0; t < 16; t++) {
            int idx = tid + t * 256;
            int r = idx >> 4, c4 = (idx & 15) * 4;
            float4 a = *(const float4*)&vptr[(size_t)(st * 256 + r) * DHH + c4];
            *(float4*)&buf[r * 68 + c4] = a;
        }
        __syncthreads();
#pragma unroll 4
        for (int kk = 0; kk < 64; kk++) {
            int kl = g * 64 + kk;           // local row in this V stage
            float4 b0 = *(const float4*)&buf[kl * 68 + bc * 8];
            float4 b1 = *(const float4*)&buf[kl * 68 + bc * 8 + 4];
            float b[8] = {b0.x, b0.y, b0.z, b0.w, b1.x, b1.y, b1.z, b1.w};
            int kcol = st * 256 + kl;
            float p[8];
#pragma unroll
            for (int i = 0; i < 8; i++)
                p[i] = sc[(wq2 * 32 + ar + 4 * i) * SCP + kcol];
#pragma unroll
            for (int i = 0; i < 8; i++)
#pragma unroll
                for (int j = 0; j < 8; j++) acc2[i][j] = fmaf(p[i], b[j], acc2[i][j]);
        }
    }

    // ---- phase 5: split-k tree reduction in smem (reuse sc) ----
    float* part = sc;                       // two tiles of 64 x 68
    __syncthreads();                        // sc reads done
    if (g >= 2) {
#pragma unroll
        for (int i = 0; i < 8; i++) {
            int q = wq2 * 32 + ar + 4 * i;
            float* p0 = &part[(g - 2) * 4352 + q * 68 + bc * 8];
            *(float4*)p0       = make_float4(acc2[i][0], acc2[i][1], acc2[i][2], acc2[i][3]);
            *(float4*)(p0 + 4) = make_float4(acc2[i][4], acc2[i][5], acc2[i][6], acc2[i][7]);
        }
    }
    __syncthreads();
    if (g < 2) {
#pragma unroll
        for (int i = 0; i < 8; i++) {
            int q = wq2 * 32 + ar + 4 * i;
            const float* p0 = &part[g * 4352 + q * 68 + bc * 8];
            float4 r0 = *(const float4*)p0, r1 = *(const float4*)(p0 + 4);
            acc2[i][0] += r0.x; acc2[i][1] += r0.y; acc2[i][2] += r0.z; acc2[i][3] += r0.w;
            acc2[i][4] += r1.x; acc2[i][5] += r1.y; acc2[i][6] += r1.z; acc2[i][7] += r1.w;
        }
    }
    __syncthreads();
    if (g == 1) {
#pragma unroll
        for (int i = 0; i < 8; i++) {
            int q = wq2 * 32 + ar + 4 * i;
            float* p0 = &part[q * 68 + bc * 8];
            *(float4*)p0       = make_float4(acc2[i][0], acc2[i][1], acc2[i][2], acc2[i][3]);
            *(float4*)(p0 + 4) = make_float4(acc2[i][4], acc2[i][5], acc2[i][6], acc2[i][7]);
        }
    }
    __syncthreads();
    if (g == 0) {
        int cc = hh * 64 + bc * 8;
#pragma unroll
        for (int i = 0; i < 8; i++) {
            int q = wq2 * 32 + ar + 4 * i;
            const float* p0 = &part[q * 68 + bc * 8];
            float4 r0 = *(const float4*)p0, r1 = *(const float4*)(p0 + 4);
            float rv = rinv[q];
            float4 o0 = make_float4((acc2[i][0] + r0.x) * rv, (acc2[i][1] + r0.y) * rv,
                                    (acc2[i][2] + r0.z) * rv, (acc2[i][3] + r0.w) * rv);
            float4 o1 = make_float4((acc2[i][4] + r1.x) * rv, (acc2[i][5] + r1.y) * rv,
                                    (acc2[i][6] + r1.z) * rv, (acc2[i][7] + r1.w) * rv);
            int qg = qt * 64 + q;
            size_t o = OUT_CTX + ((size_t)bb * SS + qg) * DD + cc;
            *(float4*)&out[o]     = o0;
            *(float4*)&out[o + 4] = o1;
            if (qg == 0) {
                *(float4*)&out[(size_t)bb * DD + cc]     = o0;
                *(float4*)&out[(size_t)bb * DD + cc + 4] = o1;
            }
        }
    }
}

// ============================================================
extern "C" void kernel_launch(void* const* d_in, const int* in_sizes, int n_in,
                              void* d_out, int out_size) {
    const int*   x_seq    = (const int*)  d_in[0];
    const int*   mask     = (const int*)  d_in[1];
    const float* word_emb = (const float*)d_in[2];
    const float* pos_emb  = (const float*)d_in[3];
    const float* ln_w     = (const float*)d_in[4];
    const float* ln_b     = (const float*)d_in[5];
    const float* wq       = (const float*)d_in[6];
    const float* bq       = (const float*)d_in[7];
    const float* wk       = (const float*)d_in[8];
    const float* bk       = (const float*)d_in[9];
    const float* wv       = (const float*)d_in[10];
    const float* bv       = (const float*)d_in[11];
    float* out = (float*)d_out;

    embed_ln_kernel<<<TT, 128>>>(x_seq, word_emb, pos_emb, ln_w, ln_b);

    dim3 ggrid(TT / 128, DD / 128, 3);
    qkv_gemm_kernel<<<ggrid, 256>>>(wq, bq, wk, bk, wv, bv);

    cudaFuncSetAttribute(attn_kernel, cudaFuncAttributeMaxDynamicSharedMemorySize,
                         (int)ATTN_SMEM);
    dim3 agrid(SS / 64, HH, BB);
    attn_kernel<<<agrid, 256, ATTN_SMEM>>>(mask, out);
}

// round 4
// speedup vs baseline: 1.2713x; 1.0307x over previous
#include <cuda_runtime.h>
#include <math.h>
#include <stdint.h>

#define BB 32
#define SS 512
#define DD 512
#define HH 8
#define DHH 64
#define TT (BB*SS)   // 16384 tokens

// ---- scratch (__device__ globals are allowed; no dynamic alloc) ----
__device__ float g_h[(size_t)TT * DD];                 // LN output
__device__ float g_q[(size_t)BB * HH * SS * DHH];      // [b,h,s,d]
__device__ float g_k[(size_t)BB * HH * SS * DHH];
__device__ float g_v[(size_t)BB * HH * SS * DHH];

// output layout: [ ctx0: B*D ][ ctx: B*S*D ][ probs: B*H*S*S ]
#define OUT_CTX   ((size_t)BB * DD)
#define OUT_PROBS (OUT_CTX + (size_t)BB * SS * DD)

// ============================================================
// Kernel 1: embedding + positional + LayerNorm (float4 path)
// ============================================================
__global__ void embed_ln_kernel(const int* __restrict__ x_seq,
                                const float* __restrict__ word_emb,
                                const float* __restrict__ pos_emb,
                                const float* __restrict__ ln_w,
                                const float* __restrict__ ln_b) {
    int row = blockIdx.x;
    int s   = row & (SS - 1);
    int tid = threadIdx.x;       // 128
    int x   = x_seq[row];
    const float4* we = (const float4*)(word_emb + (size_t)x * DD);
    const float4* pe = (const float4*)(pos_emb  + (size_t)s * DD);

    float4 w4 = we[tid], p4 = pe[tid];
    float4 v4 = make_float4(w4.x + p4.x, w4.y + p4.y, w4.z + p4.z, w4.w + p4.w);
    float sum = v4.x + v4.y + v4.z + v4.w;

    __shared__ float red[4];
#pragma unroll
    for (int o = 16; o > 0; o >>= 1) sum += __shfl_xor_sync(~0u, sum, o);
    if ((tid & 31) == 0) red[tid >> 5] = sum;
    __syncthreads();
    float mu = (red[0] + red[1] + red[2] + red[3]) * (1.0f / DD);
    __syncthreads();

    float dx = v4.x - mu, dy = v4.y - mu, dz = v4.z - mu, dw = v4.w - mu;
    float sq = dx * dx + dy * dy + dz * dz + dw * dw;
#pragma unroll
    for (int o = 16; o > 0; o >>= 1) sq += __shfl_xor_sync(~0u, sq, o);
    if ((tid & 31) == 0) red[tid >> 5] = sq;
    __syncthreads();
    float var = (red[0] + red[1] + red[2] + red[3]) * (1.0f / DD);
    float rstd = rsqrtf(var + 1e-5f);

    float4 lw = ((const float4*)ln_w)[tid];
    float4 lb = ((const float4*)ln_b)[tid];
    float4 o4;
    o4.x = dx * rstd * lw.x + lb.x;
    o4.y = dy * rstd * lw.y + lb.y;
    o4.z = dz * rstd * lw.z + lb.z;
    o4.w = dw * rstd * lw.w + lb.w;
    ((float4*)(g_h + (size_t)row * DD))[tid] = o4;
}

// ============================================================
// tf32 helpers: split fp32 -> (hi, lo) both valid tf32 patterns
// ============================================================
__device__ __forceinline__ float2 tf32_split(float x) {
    uint32_t hb;
    asm("cvt.rna.tf32.f32 %0, %1;" : "=r"(hb) : "f"(x));
    float hf = __uint_as_float(hb);
    float lo = x - hf;
    uint32_t lb;
    asm("cvt.rna.tf32.f32 %0, %1;" : "=r"(lb) : "f"(lo));
    return make_float2(hf, __uint_as_float(lb));
}

__device__ __forceinline__ void mma_tf32(float* c,
        uint32_t a0, uint32_t a1, uint32_t a2, uint32_t a3,
        uint32_t b0, uint32_t b1) {
    asm("mma.sync.aligned.m16n8k8.row.col.f32.tf32.tf32.f32 "
        "{%0,%1,%2,%3}, {%4,%5,%6,%7}, {%8,%9}, {%0,%1,%2,%3};"
        : "+f"(c[0]), "+f"(c[1]), "+f"(c[2]), "+f"(c[3])
        : "r"(a0), "r"(a1), "r"(a2), "r"(a3), "r"(b0), "r"(b1));
}

// 3xTF32: acc += A*B with near-fp32 accuracy (hi*hi + hi*lo + lo*hi)
__device__ __forceinline__ void mma3(float* c, const float2* a, const float2* b) {
    uint32_t ah[4], al[4];
#pragma unroll
    for (int i = 0; i < 4; i++) { ah[i] = __float_as_uint(a[i].x); al[i] = __float_as_uint(a[i].y); }
    uint32_t bh0 = __float_as_uint(b[0].x), bl0 = __float_as_uint(b[0].y);
    uint32_t bh1 = __float_as_uint(b[1].x), bl1 = __float_as_uint(b[1].y);
    mma_tf32(c, ah[0], ah[1], ah[2], ah[3], bh0, bh1);
    mma_tf32(c, ah[0], ah[1], ah[2], ah[3], bl0, bl1);
    mma_tf32(c, al[0], al[1], al[2], al[3], bh0, bh1);
}

// ============================================================
// Kernel 2: QKV projection via 3xTF32 mma.sync
// CTA tile 128x128, 8 warps (warp_m = warp&1, warp_n = warp>>1),
// warp tile 64x32, k-chunk 16, smem (hi,lo)-interleaved float2
// ============================================================
#define S2 21   // float2 stride per row (16 k + pad)

__global__ void __launch_bounds__(256, 2) qkv_mma_kernel(
        const float* __restrict__ wq, const float* __restrict__ bq,
        const float* __restrict__ wk, const float* __restrict__ bk,
        const float* __restrict__ wv, const float* __restrict__ bv) {
    const float* W; const float* bias; float* out;
    int z = blockIdx.z;
    if      (z == 0) { W = wq; bias = bq; out = g_q; }
    else if (z == 1) { W = wk; bias = bk; out = g_k; }
    else             { W = wv; bias = bv; out = g_v; }

    __shared__ float2 As[128 * S2];   // [row][k] (hi,lo)
    __shared__ float2 Bs[128 * S2];   // [col][k] (hi,lo)

    int tid  = threadIdx.x;
    int warp = tid >> 5, lane = tid & 31;
    int g    = lane >> 2, tig = lane & 3;    // mma lane decomposition
    int wm = warp & 1, wn = warp >> 1;       // 2 x 4 warp grid
    int row0 = blockIdx.x * 128;
    int col0 = blockIdx.y * 128;
    int ar = lane & 3, bc = lane >> 2;       // g2s enumeration

    // prefetch first chunk
    float4 pa[2], pb[2];
#pragma unroll
    for (int t = 0; t < 2; t++) {
        int r = ((t * 8 + warp) << 3) + bc;
        pa[t] = *(const float4*)&g_h[(size_t)(row0 + r) * DD + ar * 4];
        pb[t] = *(const float4*)&W  [(size_t)(col0 + r) * DD + ar * 4];
    }

    float acc[4][4][4] = {};   // [mf][nf][reg]

    for (int k0 = 0; k0 < DD; k0 += 16) {
        __syncthreads();
#pragma unroll
        for (int t = 0; t < 2; t++) {
            int r  = ((t * 8 + warp) << 3) + bc;
            int c4 = ar * 4;
            As[r * S2 + c4 + 0] = tf32_split(pa[t].x);
            As[r * S2 + c4 + 1] = tf32_split(pa[t].y);
            As[r * S2 + c4 + 2] = tf32_split(pa[t].z);
            As[r * S2 + c4 + 3] = tf32_split(pa[t].w);
            Bs[r * S2 + c4 + 0] = tf32_split(pb[t].x);
            Bs[r * S2 + c4 + 1] = tf32_split(pb[t].y);
            Bs[r * S2 + c4 + 2] = tf32_split(pb[t].z);
            Bs[r * S2 + c4 + 3] = tf32_split(pb[t].w);
        }
        __syncthreads();
        int kn = k0 + 16;
        if (kn < DD) {
#pragma unroll
            for (int t = 0; t < 2; t++) {
                int r = ((t * 8 + warp) << 3) + bc;
                pa[t] = *(const float4*)&g_h[(size_t)(row0 + r) * DD + kn + ar * 4];
                pb[t] = *(const float4*)&W  [(size_t)(col0 + r) * DD + kn + ar * 4];
            }
        }
#pragma unroll
        for (int k8 = 0; k8 < 2; k8++) {
            int kb = k8 * 8;
            // B fragments for 4 n-frags
            float2 bf[4][2];
#pragma unroll
            for (int nf = 0; nf < 4; nf++) {
                int cb = wn * 32 + nf * 8 + g;
                bf[nf][0] = Bs[cb * S2 + kb + tig];
                bf[nf][1] = Bs[cb * S2 + kb + tig + 4];
            }
#pragma unroll
            for (int mf = 0; mf < 4; mf++) {
                int rb = wm * 64 + mf * 16;
                float2 af[4];
                af[0] = As[(rb + g)     * S2 + kb + tig];
                af[1] = As[(rb + g + 8) * S2 + kb + tig];
                af[2] = As[(rb + g)     * S2 + kb + tig + 4];
                af[3] = As[(rb + g + 8) * S2 + kb + tig + 4];
#pragma unroll
                for (int nf = 0; nf < 4; nf++)
                    mma3(acc[mf][nf], af, bf[nf]);
            }
        }
    }

    // ---- epilogue: bias + scatter to [b,h,s,dh] ----
#pragma unroll
    for (int nf = 0; nf < 4; nf++) {
        int col = col0 + wn * 32 + nf * 8 + 2 * tig;
        int h_ = col >> 6, d_ = col & 63;
        float2 bi = *(const float2*)&bias[col];
#pragma unroll
        for (int mf = 0; mf < 4; mf++) {
#pragma unroll
            for (int half = 0; half < 2; half++) {
                int t  = row0 + wm * 64 + mf * 16 + g + half * 8;
                int b_ = t >> 9, s_ = t & 511;
                float2 o2 = make_float2(acc[mf][nf][half * 2 + 0] + bi.x,
                                        acc[mf][nf][half * 2 + 1] + bi.y);
                *(float2*)&out[((((size_t)b_ * HH + h_) * SS) + s_) * DHH + d_] = o2;
            }
        }
    }
}

// ============================================================
// Kernel 3: attention (unchanged from round 3 — scalar fp32)
// ============================================================
#define SCP 516
#define QTS 68
#define KTS 260
#define SC_FLOATS   (64 * SCP)
#define QT_FLOATS   (64 * QTS)
#define BUF_FLOATS  (256 * 68)
#define ATTN_SMEM ((SC_FLOATS + QT_FLOATS + BUF_FLOATS + 512 + 64) * sizeof(float))

__global__ void __launch_bounds__(256, 1) attn_kernel(const int* __restrict__ mask,
                                                      float* __restrict__ out) {
    int qt = blockIdx.x, hh = blockIdx.y, bb = blockIdx.z;
    extern __shared__ float sm[];
    float* sc   = sm;
    float* qT   = sc + SC_FLOATS;
    float* buf  = qT + QT_FLOATS;
    float* msm  = buf + BUF_FLOATS;
    float* rinv = msm + 512;

    int tid  = threadIdx.x;
    int warp = tid >> 5, lane = tid & 31;
    int ar = lane & 3, bc = lane >> 2;
    size_t bh = (size_t)bb * HH + hh;
    const float* qptr = g_q + (bh * SS + (size_t)qt * 64) * DHH;
    const float* kptr = g_k + bh * SS * DHH;
    const float* vptr = g_v + bh * SS * DHH;

#pragma unroll
    for (int t = 0; t < 4; t++) {
        int r  = warp * 8 + bc;
        int c4 = t * 16 + ar * 4;
        float4 a = *(const float4*)&qptr[(size_t)r * DHH + c4];
        qT[(c4 + 0) * QTS + r] = a.x;
        qT[(c4 + 1) * QTS + r] = a.y;
        qT[(c4 + 2) * QTS + r] = a.z;
        qT[(c4 + 3) * QTS + r] = a.w;
    }
    for (int i = tid; i < SS; i += 256)
        msm[i] = (1.0f - (float)mask[(size_t)bb * SS + i]) * -10000.0f;

    int wq = warp >> 2, wk = warp & 3;
    for (int kt = 0; kt < 2; kt++) {
        __syncthreads();
#pragma unroll
        for (int t = 0; t < 16; t++) {
            int rb = (t >> 2) * 8 + warp;
            int r  = rb * 8 + bc;
            int c4 = (t & 3) * 16 + ar * 4;
            float4 a = *(const float4*)&kptr[(size_t)(kt * 256 + r) * DHH + c4];
            buf[(c4 + 0) * KTS + r] = a.x;
            buf[(c4 + 1) * KTS + r] = a.y;
            buf[(c4 + 2) * KTS + r] = a.z;
            buf[(c4 + 3) * KTS + r] = a.w;
        }
        __syncthreads();
        float acc[8][8] = {};
#pragma unroll 4
        for (int kk = 0; kk < 64; kk++) {
            float4 a0 = *(const float4*)&qT[kk * QTS + wq * 32 + ar * 8];
            float4 a1 = *(const float4*)&qT[kk * QTS + wq * 32 + ar * 8 + 4];
            float4 b0 = *(const float4*)&buf[kk * KTS + wk * 64 + bc * 8];
            float4 b1 = *(const float4*)&buf[kk * KTS + wk * 64 + bc * 8 + 4];
            float a[8] = {a0.x, a0.y, a0.z, a0.w, a1.x, a1.y, a1.z, a1.w};
            float b[8] = {b0.x, b0.y, b0.z, b0.w, b1.x, b1.y, b1.z, b1.w};
#pragma unroll
            for (int i = 0; i < 8; i++)
#pragma unroll
                for (int j = 0; j < 8; j++) acc[i][j] = fmaf(a[i], b[j], acc[i][j]);
        }
        int col = kt * 256 + wk * 64 + bc * 8;
        float4 m0 = *(const float4*)&msm[col];
        float4 m1 = *(const float4*)&msm[col + 4];
#pragma unroll
        for (int i = 0; i < 8; i++) {
            int q = wq * 32 + ar * 8 + i;
            *(float4*)&sc[q * SCP + col] =
                make_float4(acc[i][0] * 0.125f * m0.x, acc[i][1] * 0.125f * m0.y,
                            acc[i][2] * 0.125f * m0.z, acc[i][3] * 0.125f * m0.w);
            *(float4*)&sc[q * SCP + col + 4] =
                make_float4(acc[i][4] * 0.125f * m1.x, acc[i][5] * 0.125f * m1.y,
                            acc[i][6] * 0.125f * m1.z, acc[i][7] * 0.125f * m1.w);
        }
    }
    __syncthreads();

    {
        int r = tid >> 2, l4 = tid & 3;
        float mx = -INFINITY;
        for (int c = l4 * 4; c < SS; c += 16) {
            float4 s4 = *(const float4*)&sc[r * SCP + c];
            mx = fmaxf(mx, fmaxf(fmaxf(s4.x, s4.y), fmaxf(s4.z, s4.w)));
        }
        mx = fmaxf(mx, __shfl_xor_sync(~0u, mx, 1));
        mx = fmaxf(mx, __shfl_xor_sync(~0u, mx, 2));
        float sum = 0.f;
        for (int c = l4 * 4; c < SS; c += 16) {
            float4 s4 = *(const float4*)&sc[r * SCP + c];
            s4.x = __expf(s4.x - mx); s4.y = __expf(s4.y - mx);
            s4.z = __expf(s4.z - mx); s4.w = __expf(s4.w - mx);
            *(float4*)&sc[r * SCP + c] = s4;
            sum += s4.x + s4.y + s4.z + s4.w;
        }
        sum += __shfl_xor_sync(~0u, sum, 1);
        sum += __shfl_xor_sync(~0u, sum, 2);
        if (l4 == 0) rinv[r] = 1.0f / sum;
    }
    __syncthreads();

    {
        float* pbase = out + OUT_PROBS + (bh * SS + (size_t)qt * 64) * SS;
#pragma unroll
        for (int t = 0; t < 32; t++) {
            int idx = tid + t * 256;
            int r = idx >> 7, c = (idx & 127) * 4;
            float rv = rinv[r];
            float4 e4 = *(const float4*)&sc[r * SCP + c];
            *(float4*)&pbase[(size_t)r * SS + c] =
                make_float4(e4.x * rv, e4.y * rv, e4.z * rv, e4.w * rv);
        }
    }

    int g   = warp >> 1;
    int wq2 = warp & 1;
    float acc2[8][8] = {};
    for (int st = 0; st < 2; st++) {
        __syncthreads();
#pragma unroll
        for (int t = 0; t < 16; t++) {
            int idx = tid + t * 256;
            int r = idx >> 4, c4 = (idx & 15) * 4;
            float4 a = *(const float4*)&vptr[(size_t)(st * 256 + r) * DHH + c4];
            *(float4*)&buf[r * 68 + c4] = a;
        }
        __syncthreads();
#pragma unroll 4
        for (int kk = 0; kk < 64; kk++) {
            int kl = g * 64 + kk;
            float4 b0 = *(const float4*)&buf[kl * 68 + bc * 8];
            float4 b1 = *(const float4*)&buf[kl * 68 + bc * 8 + 4];
            float b[8] = {b0.x, b0.y, b0.z, b0.w, b1.x, b1.y, b1.z, b1.w};
            int kcol = st * 256 + kl;
            float p[8];
#pragma unroll
            for (int i = 0; i < 8; i++)
                p[i] = sc[(wq2 * 32 + ar + 4 * i) * SCP + kcol];
#pragma unroll
            for (int i = 0; i < 8; i++)
#pragma unroll
                for (int j = 0; j < 8; j++) acc2[i][j] = fmaf(p[i], b[j], acc2[i][j]);
        }
    }

    float* part = sc;
    __syncthreads();
    if (g >= 2) {
#pragma unroll
        for (int i = 0; i < 8; i++) {
            int q = wq2 * 32 + ar + 4 * i;
            float* p0 = &part[(g - 2) * 4352 + q * 68 + bc * 8];
            *(float4*)p0       = make_float4(acc2[i][0], acc2[i][1], acc2[i][2], acc2[i][3]);
            *(float4*)(p0 + 4) = make_float4(acc2[i][4], acc2[i][5], acc2[i][6], acc2[i][7]);
        }
    }
    __syncthreads();
    if (g < 2) {
#pragma unroll
        for (int i = 0; i < 8; i++) {
            int q = wq2 * 32 + ar + 4 * i;
            const float* p0 = &part[g * 4352 + q * 68 + bc * 8];
            float4 r0 = *(const float4*)p0, r1 = *(const float4*)(p0 + 4);
            acc2[i][0] += r0.x; acc2[i][1] += r0.y; acc2[i][2] += r0.z; acc2[i][3] += r0.w;
            acc2[i][4] += r1.x; acc2[i][5] += r1.y; acc2[i][6] += r1.z; acc2[i][7] += r1.w;
        }
    }
    __syncthreads();
    if (g == 1) {
#pragma unroll
        for (int i = 0; i < 8; i++) {
            int q = wq2 * 32 + ar + 4 * i;
            float* p0 = &part[q * 68 + bc * 8];
            *(float4*)p0       = make_float4(acc2[i][0], acc2[i][1], acc2[i][2], acc2[i][3]);
            *(float4*)(p0 + 4) = make_float4(acc2[i][4], acc2[i][5], acc2[i][6], acc2[i][7]);
        }
    }
    __syncthreads();
    if (g == 0) {
        int cc = hh * 64 + bc * 8;
#pragma unroll
        for (int i = 0; i < 8; i++) {
            int q = wq2 * 32 + ar + 4 * i;
            const float* p0 = &part[q * 68 + bc * 8];
            float4 r0 = *(const float4*)p0, r1 = *(const float4*)(p0 + 4);
            float rv = rinv[q];
            float4 o0 = make_float4((acc2[i][0] + r0.x) * rv, (acc2[i][1] + r0.y) * rv,
                                    (acc2[i][2] + r0.z) * rv, (acc2[i][3] + r0.w) * rv);
            float4 o1 = make_float4((acc2[i][4] + r1.x) * rv, (acc2[i][5] + r1.y) * rv,
                                    (acc2[i][6] + r1.z) * rv, (acc2[i][7] + r1.w) * rv);
            int qg = qt * 64 + q;
            size_t o = OUT_CTX + ((size_t)bb * SS + qg) * DD + cc;
            *(float4*)&out[o]     = o0;
            *(float4*)&out[o + 4] = o1;
            if (qg == 0) {
                *(float4*)&out[(size_t)bb * DD + cc]     = o0;
                *(float4*)&out[(size_t)bb * DD + cc + 4] = o1;
            }
        }
    }
}

// ============================================================
extern "C" void kernel_launch(void* const* d_in, const int* in_sizes, int n_in,
                              void* d_out, int out_size) {
    const int*   x_seq    = (const int*)  d_in[0];
    const int*   mask     = (const int*)  d_in[1];
    const float* word_emb = (const float*)d_in[2];
    const float* pos_emb  = (const float*)d_in[3];
    const float* ln_w     = (const float*)d_in[4];
    const float* ln_b     = (const float*)d_in[5];
    const float* wq       = (const float*)d_in[6];
    const float* bq       = (const float*)d_in[7];
    const float* wk       = (const float*)d_in[8];
    const float* bk       = (const float*)d_in[9];
    const float* wv       = (const float*)d_in[10];
    const float* bv       = (const float*)d_in[11];
    float* out = (float*)d_out;

    embed_ln_kernel<<<TT, 128>>>(x_seq, word_emb, pos_emb, ln_w, ln_b);

    dim3 ggrid(TT / 128, DD / 128, 3);
    qkv_mma_kernel<<<ggrid, 256>>>(wq, bq, wk, bk, wv, bv);

    cudaFuncSetAttribute(attn_kernel, cudaFuncAttributeMaxDynamicSharedMemorySize,
                         (int)ATTN_SMEM);
    dim3 agrid(SS / 64, HH, BB);
    attn_kernel<<<agrid, 256, ATTN_SMEM>>>(mask, out);
}

// round 6
// speedup vs baseline: 1.3696x; 1.0774x over previous
#include <cuda_runtime.h>
#include <math.h>
#include <stdint.h>

#define BB 32
#define SS 512
#define DD 512
#define HH 8
#define DHH 64
#define TT (BB*SS)   // 16384 tokens

// ---- scratch (__device__ globals; no dynamic alloc) ----
// A operand (LN output h), split + fragment-tiled:
// layout [rb(1024)][kb(64)][lane(32)][e(4)]  (rb = row/16, kb = col/8)
__device__ float g_ah[(size_t)1024 * 64 * 128];
__device__ float g_al[(size_t)1024 * 64 * 128];
// B operand (weights), split + fragment-tiled per z:
// layout [cb(64)][kb(64)][lane(32)][e(2)]
__device__ float g_bh[3][(size_t)64 * 64 * 64];
__device__ float g_bl[3][(size_t)64 * 64 * 64];

__device__ float g_q[(size_t)BB * HH * SS * DHH];      // [b,h,s,d]
__device__ float g_k[(size_t)BB * HH * SS * DHH];
__device__ float g_v[(size_t)BB * HH * SS * DHH];

// output layout: [ ctx0: B*D ][ ctx: B*S*D ][ probs: B*H*S*S ]
#define OUT_CTX   ((size_t)BB * DD)
#define OUT_PROBS (OUT_CTX + (size_t)BB * SS * DD)

// ============================================================
// tf32 split + mma helpers
// ============================================================
__device__ __forceinline__ float2 tf32_split(float x) {
    uint32_t hb;
    asm("cvt.rna.tf32.f32 %0, %1;" : "=r"(hb) : "f"(x));
    float hf = __uint_as_float(hb);
    float lo = x - hf;
    uint32_t lb;
    asm("cvt.rna.tf32.f32 %0, %1;" : "=r"(lb) : "f"(lo));
    return make_float2(hf, __uint_as_float(lb));
}

__device__ __forceinline__ void mma_tf32(float* c,
        uint32_t a0, uint32_t a1, uint32_t a2, uint32_t a3,
        uint32_t b0, uint32_t b1) {
    asm("mma.sync.aligned.m16n8k8.row.col.f32.tf32.tf32.f32 "
        "{%0,%1,%2,%3}, {%4,%5,%6,%7}, {%8,%9}, {%0,%1,%2,%3};"
        : "+f"(c[0]), "+f"(c[1]), "+f"(c[2]), "+f"(c[3])
        : "r"(a0), "r"(a1), "r"(a2), "r"(a3), "r"(b0), "r"(b1));
}

__device__ __forceinline__ void cp16(float* smem_dst, const float* gsrc) {
    uint32_t s = (uint32_t)__cvta_generic_to_shared(smem_dst);
    asm volatile("cp.async.ca.shared.global [%0], [%1], 16;" :: "r"(s), "l"(gsrc));
}
__device__ __forceinline__ void cp_commit() {
    asm volatile("cp.async.commit_group;");
}

// ============================================================
// Kernel 1: embed + pos + LayerNorm, writing SPLIT + TILED planes.
// One block per 16-row tile (rb). 256 threads, 8 warps.
// Warp w: rows 2w, 2w+1. Lane: row_local = 2w + (lane>>4), 32 cols.
// ============================================================
#define EMB_SMEM (2 * 16 * 512 * 4)   // hi+lo staging, 64KB

__global__ void __launch_bounds__(256) embed_ln_kernel(
        const int* __restrict__ x_seq,
        const float* __restrict__ word_emb,
        const float* __restrict__ pos_emb,
        const float* __restrict__ ln_w,
        const float* __restrict__ ln_b) {
    extern __shared__ float es[];
    float* shi = es;            // 8192 floats, tiled layout within rb
    float* slo = es + 8192;

    int rb   = blockIdx.x;               // 16-row tile
    int tid  = threadIdx.x;
    int w    = tid >> 5, lane = tid & 31;
    int rloc = 2 * w + (lane >> 4);      // 0..15
    int li   = lane & 15;                // col group
    int row  = rb * 16 + rloc;
    int s    = row & (SS - 1);
    int x    = x_seq[row];
    const float* we = word_emb + (size_t)x * DD;
    const float* pe = pos_emb  + (size_t)s * DD;

    float v[32];
    float sum = 0.f;
#pragma unroll
    for (int q = 0; q < 8; q++) {
        int c = li * 32 + q * 4;
        float4 a = *(const float4*)&we[c];
        float4 b = *(const float4*)&pe[c];
        v[q*4+0] = a.x + b.x; v[q*4+1] = a.y + b.y;
        v[q*4+2] = a.z + b.z; v[q*4+3] = a.w + b.w;
        sum += v[q*4+0] + v[q*4+1] + v[q*4+2] + v[q*4+3];
    }
    // reduce within 16-lane half-warp (offsets 8..1 stay in-half)
#pragma unroll
    for (int o = 8; o > 0; o >>= 1) sum += __shfl_xor_sync(~0u, sum, o);
    float mu = sum * (1.0f / DD);
    float sq = 0.f;
#pragma unroll
    for (int q = 0; q < 32; q++) { float d = v[q] - mu; sq += d * d; }
#pragma unroll
    for (int o = 8; o > 0; o >>= 1) sq += __shfl_xor_sync(~0u, sq, o);
    float rstd = rsqrtf(sq * (1.0f / DD) + 1e-5f);

    int g  = rloc & 7, hh_ = rloc >> 3;
#pragma unroll
    for (int q = 0; q < 32; q++) {
        int c = li * 32 + q;
        float o = (v[q] - mu) * rstd * ln_w[c] + ln_b[c];
        float2 sp = tf32_split(o);
        int kb = c >> 3, tig = c & 3, ch = (c >> 2) & 1;
        int ta = (kb * 32 + g * 4 + tig) * 4 + hh_ + 2 * ch;
        shi[ta] = sp.x;
        slo[ta] = sp.y;
    }
    __syncthreads();
    // coalesced copy to global planes (rb tile is contiguous: 8192 floats)
    size_t base = (size_t)rb * 8192;
#pragma unroll
    for (int r = 0; r < 8; r++) {
        int i = (tid + r * 256) * 4;
        *(float4*)&g_ah[base + i] = *(const float4*)&shi[i];
        *(float4*)&g_al[base + i] = *(const float4*)&slo[i];
    }
}

// ============================================================
// Kernel 1b: split+tile the three weight matrices (one-shot cheap)
// ============================================================
__global__ void split_w_kernel(const float* __restrict__ wq,
                               const float* __restrict__ wk,
                               const float* __restrict__ wv) {
    int idx = blockIdx.x * 256 + threadIdx.x;   // 3*512*512 total
    int z = idx >> 18;
    int rem = idx & ((1 << 18) - 1);
    int n = rem >> 9, k = rem & 511;
    const float* W = (z == 0) ? wq : (z == 1) ? wk : wv;
    float2 sp = tf32_split(W[(size_t)n * DD + k]);
    int cb = n >> 3, kb = k >> 3, g = n & 7, tig = k & 3, e = (k >> 2) & 1;
    size_t a = ((size_t)(cb * 64 + kb) * 32 + g * 4 + tig) * 2 + e;
    g_bh[z][a] = sp.x;
    g_bl[z][a] = sp.y;
}

// ============================================================
// Kernel 2: QKV GEMM via 3xTF32 mma.sync, cp.async double buffer
// CTA 128x128, 8 warps (wm=warp&1 -> 64 rows, wn=warp>>1 -> 32 cols)
// k-chunk 16 (2 k8 blocks), 32 chunks.
// stage layout (floats): Ah[2048] Al[2048] Bh[2048] Bl[2048] = 8192/stage
// ============================================================
#define QKV_SMEM (2 * 8192 * 4)   // 64KB

__global__ void __launch_bounds__(256) qkv_mma_kernel(
        const float* __restrict__ bq, const float* __restrict__ bk,
        const float* __restrict__ bv) {
    const float* bias; float* out;
    int z = blockIdx.z;
    if      (z == 0) { bias = bq; out = g_q; }
    else if (z == 1) { bias = bk; out = g_k; }
    else             { bias = bv; out = g_v; }
    const float* Bh = g_bh[z];
    const float* Bl = g_bl[z];

    extern __shared__ float smem[];
    int tid  = threadIdx.x;
    int warp = tid >> 5, lane = tid & 31;
    int wm = warp & 1, wn = warp >> 1;
    int rb0 = blockIdx.x * 8;       // row tile /16
    int cb0 = blockIdx.y * 16;      // col tile /8

    float acc[4][4][4] = {};

    // ---- copy chunk kc into stage st ----
    auto copy_chunk = [&](float* st, int kc) {
#pragma unroll
        for (int r = 0; r < 2; r++) {
            int f = (tid + r * 256) * 4;             // 0..2044
            int i = f >> 8, j = (f >> 7) & 1, t = f & 127;
            size_t src = ((size_t)(rb0 + i) * 64 + kc * 2 + j) * 128 + t;
            cp16(&st[f],        &g_ah[src]);
            cp16(&st[2048 + f], &g_al[src]);
        }
#pragma unroll
        for (int r = 0; r < 2; r++) {
            int f = (tid + r * 256) * 4;
            int i = f >> 7, j = (f >> 6) & 1, t = f & 63;
            size_t src = ((size_t)(cb0 + i) * 64 + kc * 2 + j) * 64 + t;
            cp16(&st[4096 + f], &Bh[src]);
            cp16(&st[6144 + f], &Bl[src]);
        }
    };

    copy_chunk(smem, 0);
    cp_commit();

    for (int kc = 0; kc < 32; kc++) {
        float* cur = smem + (kc & 1) * 8192;
        if (kc < 31) {
            copy_chunk(smem + ((kc + 1) & 1) * 8192, kc + 1);
            cp_commit();
            asm volatile("cp.async.wait_group 1;");
        } else {
            asm volatile("cp.async.wait_group 0;");
        }
        __syncthreads();

#pragma unroll
        for (int j = 0; j < 2; j++) {
            float2 bhf[4], blf[4];
#pragma unroll
            for (int nf = 0; nf < 4; nf++) {
                int bi = (((wn * 4 + nf) * 2 + j) * 32 + lane) * 2;
                bhf[nf] = *(const float2*)&cur[4096 + bi];
                blf[nf] = *(const float2*)&cur[6144 + bi];
            }
#pragma unroll
            for (int mf = 0; mf < 4; mf++) {
                int ai = (((wm * 4 + mf) * 2 + j) * 32 + lane) * 4;
                float4 ah = *(const float4*)&cur[ai];
                float4 al = *(const float4*)&cur[2048 + ai];
                uint32_t ah0 = __float_as_uint(ah.x), ah1 = __float_as_uint(ah.y);
                uint32_t ah2 = __float_as_uint(ah.z), ah3 = __float_as_uint(ah.w);
                uint32_t al0 = __float_as_uint(al.x), al1 = __float_as_uint(al.y);
                uint32_t al2 = __float_as_uint(al.z), al3 = __float_as_uint(al.w);
#pragma unroll
                for (int nf = 0; nf < 4; nf++) {
                    uint32_t bh0 = __float_as_uint(bhf[nf].x);
                    uint32_t bh1 = __float_as_uint(bhf[nf].y);
                    uint32_t bl0 = __float_as_uint(blf[nf].x);
                    uint32_t bl1 = __float_as_uint(blf[nf].y);
                    mma_tf32(acc[mf][nf], ah0, ah1, ah2, ah3, bh0, bh1);
                    mma_tf32(acc[mf][nf], ah0, ah1, ah2, ah3, bl0, bl1);
                    mma_tf32(acc[mf][nf], al0, al1, al2, al3, bh0, bh1);
                }
            }
        }
        __syncthreads();
    }

    // ---- epilogue: bias + scatter to [b,h,s,dh] ----
    int g   = lane >> 2, tig = lane & 3;
    int row0 = blockIdx.x * 128, col0 = blockIdx.y * 128;
#pragma unroll
    for (int nf = 0; nf < 4; nf++) {
        int col = col0 + wn * 32 + nf * 8 + 2 * tig;
        int h_ = col >> 6, d_ = col & 63;
        float2 bi = *(const float2*)&bias[col];
#pragma unroll
        for (int mf = 0; mf < 4; mf++) {
#pragma unroll
            for (int half = 0; half < 2; half++) {
                int t  = row0 + wm * 64 + mf * 16 + g + half * 8;
                int b_ = t >> 9, s_ = t & 511;
                float2 o2 = make_float2(acc[mf][nf][half * 2 + 0] + bi.x,
                                        acc[mf][nf][half * 2 + 1] + bi.y);
                *(float2*)&out[((((size_t)b_ * HH + h_) * SS) + s_) * DHH + d_] = o2;
            }
        }
    }
}

// ============================================================
// Kernel 3: attention (validated scalar fp32, unchanged)
// ============================================================
#define SCP 516
#define QTS 68
#define KTS 260
#define SC_FLOATS   (64 * SCP)
#define QT_FLOATS   (64 * QTS)
#define BUF_FLOATS  (256 * 68)
#define ATTN_SMEM ((SC_FLOATS + QT_FLOATS + BUF_FLOATS + 512 + 64) * sizeof(float))

__global__ void __launch_bounds__(256, 1) attn_kernel(const int* __restrict__ mask,
                                                      float* __restrict__ out) {
    int qt = blockIdx.x, hh = blockIdx.y, bb = blockIdx.z;
    extern __shared__ float sm[];
    float* sc   = sm;
    float* qT   = sc + SC_FLOATS;
    float* buf  = qT + QT_FLOATS;
    float* msm  = buf + BUF_FLOATS;
    float* rinv = msm + 512;

    int tid  = threadIdx.x;
    int warp = tid >> 5, lane = tid & 31;
    int ar = lane & 3, bc = lane >> 2;
    size_t bh = (size_t)bb * HH + hh;
    const float* qptr = g_q + (bh * SS + (size_t)qt * 64) * DHH;
    const float* kptr = g_k + bh * SS * DHH;
    const float* vptr = g_v + bh * SS * DHH;

#pragma unroll
    for (int t = 0; t < 4; t++) {
        int r  = warp * 8 + bc;
        int c4 = t * 16 + ar * 4;
        float4 a = *(const float4*)&qptr[(size_t)r * DHH + c4];
        qT[(c4 + 0) * QTS + r] = a.x;
        qT[(c4 + 1) * QTS + r] = a.y;
        qT[(c4 + 2) * QTS + r] = a.z;
        qT[(c4 + 3) * QTS + r] = a.w;
    }
    for (int i = tid; i < SS; i += 256)
        msm[i] = (1.0f - (float)mask[(size_t)bb * SS + i]) * -10000.0f;

    int wq = warp >> 2, wk = warp & 3;
    for (int kt = 0; kt < 2; kt++) {
        __syncthreads();
#pragma unroll
        for (int t = 0; t < 16; t++) {
            int rb = (t >> 2) * 8 + warp;
            int r  = rb * 8 + bc;
            int c4 = (t & 3) * 16 + ar * 4;
            float4 a = *(const float4*)&kptr[(size_t)(kt * 256 + r) * DHH + c4];
            buf[(c4 + 0) * KTS + r] = a.x;
            buf[(c4 + 1) * KTS + r] = a.y;
            buf[(c4 + 2) * KTS + r] = a.z;
            buf[(c4 + 3) * KTS + r] = a.w;
        }
        __syncthreads();
        float acc[8][8] = {};
#pragma unroll 4
        for (int kk = 0; kk < 64; kk++) {
            float4 a0 = *(const float4*)&qT[kk * QTS + wq * 32 + ar * 8];
            float4 a1 = *(const float4*)&qT[kk * QTS + wq * 32 + ar * 8 + 4];
            float4 b0 = *(const float4*)&buf[kk * KTS + wk * 64 + bc * 8];
            float4 b1 = *(const float4*)&buf[kk * KTS + wk * 64 + bc * 8 + 4];
            float a[8] = {a0.x, a0.y, a0.z, a0.w, a1.x, a1.y, a1.z, a1.w};
            float b[8] = {b0.x, b0.y, b0.z, b0.w, b1.x, b1.y, b1.z, b1.w};
#pragma unroll
            for (int i = 0; i < 8; i++)
#pragma unroll
                for (int j = 0; j < 8; j++) acc[i][j] = fmaf(a[i], b[j], acc[i][j]);
        }
        int col = kt * 256 + wk * 64 + bc * 8;
        float4 m0 = *(const float4*)&msm[col];
        float4 m1 = *(const float4*)&msm[col + 4];
#pragma unroll
        for (int i = 0; i < 8; i++) {
            int q = wq * 32 + ar * 8 + i;
            *(float4*)&sc[q * SCP + col] =
                make_float4(acc[i][0] * 0.125f * m0.x, acc[i][1] * 0.125f * m0.y,
                            acc[i][2] * 0.125f * m0.z, acc[i][3] * 0.125f * m0.w);
            *(float4*)&sc[q * SCP + col + 4] =
                make_float4(acc[i][4] * 0.125f * m1.x, acc[i][5] * 0.125f * m1.y,
                            acc[i][6] * 0.125f * m1.z, acc[i][7] * 0.125f * m1.w);
        }
    }
    __syncthreads();

    {
        int r = tid >> 2, l4 = tid & 3;
        float mx = -INFINITY;
        for (int c = l4 * 4; c < SS; c += 16) {
            float4 s4 = *(const float4*)&sc[r * SCP + c];
            mx = fmaxf(mx, fmaxf(fmaxf(s4.x, s4.y), fmaxf(s4.z, s4.w)));
        }
        mx = fmaxf(mx, __shfl_xor_sync(~0u, mx, 1));
        mx = fmaxf(mx, __shfl_xor_sync(~0u, mx, 2));
        float sum = 0.f;
        for (int c = l4 * 4; c < SS; c += 16) {
            float4 s4 = *(const float4*)&sc[r * SCP + c];
            s4.x = __expf(s4.x - mx); s4.y = __expf(s4.y - mx);
            s4.z = __expf(s4.z - mx); s4.w = __expf(s4.w - mx);
            *(float4*)&sc[r * SCP + c] = s4;
            sum += s4.x + s4.y + s4.z + s4.w;
        }
        sum += __shfl_xor_sync(~0u, sum, 1);
        sum += __shfl_xor_sync(~0u, sum, 2);
        if (l4 == 0) rinv[r] = 1.0f / sum;
    }
    __syncthreads();

    {
        float* pbase = out + OUT_PROBS + (bh * SS + (size_t)qt * 64) * SS;
#pragma unroll
        for (int t = 0; t < 32; t++) {
            int idx = tid + t * 256;
            int r = idx >> 7, c = (idx & 127) * 4;
            float rv = rinv[r];
            float4 e4 = *(const float4*)&sc[r * SCP + c];
            *(float4*)&pbase[(size_t)r * SS + c] =
                make_float4(e4.x * rv, e4.y * rv, e4.z * rv, e4.w * rv);
        }
    }

    int g   = warp >> 1;
    int wq2 = warp & 1;
    float acc2[8][8] = {};
    for (int st = 0; st < 2; st++) {
        __syncthreads();
#pragma unroll
        for (int t = 0; t < 16; t++) {
            int idx = tid + t * 256;
            int r = idx >> 4, c4 = (idx & 15) * 4;
            float4 a = *(const float4*)&vptr[(size_t)(st * 256 + r) * DHH + c4];
            *(float4*)&buf[r * 68 + c4] = a;
        }
        __syncthreads();
#pragma unroll 4
        for (int kk = 0; kk < 64; kk++) {
            int kl = g * 64 + kk;
            float4 b0 = *(const float4*)&buf[kl * 68 + bc * 8];
            float4 b1 = *(const float4*)&buf[kl * 68 + bc * 8 + 4];
            float b[8] = {b0.x, b0.y, b0.z, b0.w, b1.x, b1.y, b1.z, b1.w};
            int kcol = st * 256 + kl;
            float p[8];
#pragma unroll
            for (int i = 0; i < 8; i++)
                p[i] = sc[(wq2 * 32 + ar + 4 * i) * SCP + kcol];
#pragma unroll
            for (int i = 0; i < 8; i++)
#pragma unroll
                for (int j = 0; j < 8; j++) acc2[i][j] = fmaf(p[i], b[j], acc2[i][j]);
        }
    }

    float* part = sc;
    __syncthreads();
    if (g >= 2) {
#pragma unroll
        for (int i = 0; i < 8; i++) {
            int q = wq2 * 32 + ar + 4 * i;
            float* p0 = &part[(g - 2) * 4352 + q * 68 + bc * 8];
            *(float4*)p0       = make_float4(acc2[i][0], acc2[i][1], acc2[i][2], acc2[i][3]);
            *(float4*)(p0 + 4) = make_float4(acc2[i][4], acc2[i][5], acc2[i][6], acc2[i][7]);
        }
    }
    __syncthreads();
    if (g < 2) {
#pragma unroll
        for (int i = 0; i < 8; i++) {
            int q = wq2 * 32 + ar + 4 * i;
            const float* p0 = &part[g * 4352 + q * 68 + bc * 8];
            float4 r0 = *(const float4*)p0, r1 = *(const float4*)(p0 + 4);
            acc2[i][0] += r0.x; acc2[i][1] += r0.y; acc2[i][2] += r0.z; acc2[i][3] += r0.w;
            acc2[i][4] += r1.x; acc2[i][5] += r1.y; acc2[i][6] += r1.z; acc2[i][7] += r1.w;
        }
    }
    __syncthreads();
    if (g == 1) {
#pragma unroll
        for (int i = 0; i < 8; i++) {
            int q = wq2 * 32 + ar + 4 * i;
            float* p0 = &part[q * 68 + bc * 8];
            *(float4*)p0       = make_float4(acc2[i][0], acc2[i][1], acc2[i][2], acc2[i][3]);
            *(float4*)(p0 + 4) = make_float4(acc2[i][4], acc2[i][5], acc2[i][6], acc2[i][7]);
        }
    }
    __syncthreads();
    if (g == 0) {
        int cc = hh * 64 + bc * 8;
#pragma unroll
        for (int i = 0; i < 8; i++) {
            int q = wq2 * 32 + ar + 4 * i;
            const float* p0 = &part[q * 68 + bc * 8];
            float4 r0 = *(const float4*)p0, r1 = *(const float4*)(p0 + 4);
            float rv = rinv[q];
            float4 o0 = make_float4((acc2[i][0] + r0.x) * rv, (acc2[i][1] + r0.y) * rv,
                                    (acc2[i][2] + r0.z) * rv, (acc2[i][3] + r0.w) * rv);
            float4 o1 = make_float4((acc2[i][4] + r1.x) * rv, (acc2[i][5] + r1.y) * rv,
                                    (acc2[i][6] + r1.z) * rv, (acc2[i][7] + r1.w) * rv);
            int qg = qt * 64 + q;
            size_t o = OUT_CTX + ((size_t)bb * SS + qg) * DD + cc;
            *(float4*)&out[o]     = o0;
            *(float4*)&out[o + 4] = o1;
            if (qg == 0) {
                *(float4*)&out[(size_t)bb * DD + cc]     = o0;
                *(float4*)&out[(size_t)bb * DD + cc + 4] = o1;
            }
        }
    }
}

// ============================================================
extern "C" void kernel_launch(void* const* d_in, const int* in_sizes, int n_in,
                              void* d_out, int out_size) {
    const int*   x_seq    = (const int*)  d_in[0];
    const int*   mask     = (const int*)  d_in[1];
    const float* word_emb = (const float*)d_in[2];
    const float* pos_emb  = (const float*)d_in[3];
    const float* ln_w     = (const float*)d_in[4];
    const float* ln_b     = (const float*)d_in[5];
    const float* wq       = (const float*)d_in[6];
    const float* bq       = (const float*)d_in[7];
    const float* wk       = (const float*)d_in[8];
    const float* bk       = (const float*)d_in[9];
    const float* wv       = (const float*)d_in[10];
    const float* bv       = (const float*)d_in[11];
    float* out = (float*)d_out;

    cudaFuncSetAttribute(embed_ln_kernel, cudaFuncAttributeMaxDynamicSharedMemorySize,
                         EMB_SMEM);
    embed_ln_kernel<<<TT / 16, 256, EMB_SMEM>>>(x_seq, word_emb, pos_emb, ln_w, ln_b);

    split_w_kernel<<<3 * 512 * 512 / 256, 256>>>(wq, wk, wv);

    cudaFuncSetAttribute(qkv_mma_kernel, cudaFuncAttributeMaxDynamicSharedMemorySize,
                         QKV_SMEM);
    dim3 ggrid(TT / 128, DD / 128, 3);
    qkv_mma_kernel<<<ggrid, 256, QKV_SMEM>>>(bq, bk, bv);

    cudaFuncSetAttribute(attn_kernel, cudaFuncAttributeMaxDynamicSharedMemorySize,
                         (int)ATTN_SMEM);
    dim3 agrid(SS / 64, HH, BB);
    attn_kernel<<<agrid, 256, ATTN_SMEM>>>(mask, out);
}

// round 7
// speedup vs baseline: 1.4497x; 1.0584x over previous
#include <cuda_runtime.h>
#include <math.h>
#include <stdint.h>

#define BB 32
#define SS 512
#define DD 512
#define HH 8
#define DHH 64
#define TT (BB*SS)   // 16384 tokens
#define NBH (BB*HH)  // 256

// ---- scratch (__device__ globals; no dynamic alloc) ----
// h (LN output) split fragment-tiled planes: [rb(1024)][kb(64)][lane(32)][e(4)]
__device__ float g_ah[(size_t)1024 * 64 * 128];
__device__ float g_al[(size_t)1024 * 64 * 128];
// weights split B-frag planes per z: [cb(64)][kb(64)][lane(32)][e(2)]
__device__ float g_bh[3][(size_t)64 * 64 * 64];
__device__ float g_bl[3][(size_t)64 * 64 * 64];
// Q split A-frag planes: [bh(256)][qf(32)][kf(8)][lane(32)][e(4)]
__device__ float gQh[(size_t)NBH * 32 * 8 * 128];
__device__ float gQl[(size_t)NBH * 32 * 8 * 128];
// K split B-frag planes (n = key): [bh][nf(64)][kf(8)][lane(32)][e(2)]
__device__ float gKh[(size_t)NBH * 64 * 8 * 64];
__device__ float gKl[(size_t)NBH * 64 * 8 * 64];
// V split B-frag planes (n = dh, k = key): [bh][kf(64)][nf(8)][lane(32)][e(2)]
__device__ float gVh[(size_t)NBH * 64 * 8 * 64];
__device__ float gVl[(size_t)NBH * 64 * 8 * 64];

// output layout: [ ctx0: B*D ][ ctx: B*S*D ][ probs: B*H*S*S ]
#define OUT_CTX   ((size_t)BB * DD)
#define OUT_PROBS (OUT_CTX + (size_t)BB * SS * DD)

// ============================================================
// tf32 split + mma helpers
// ============================================================
__device__ __forceinline__ float2 tf32_split(float x) {
    uint32_t hb;
    asm("cvt.rna.tf32.f32 %0, %1;" : "=r"(hb) : "f"(x));
    float hf = __uint_as_float(hb);
    float lo = x - hf;
    uint32_t lb;
    asm("cvt.rna.tf32.f32 %0, %1;" : "=r"(lb) : "f"(lo));
    return make_float2(hf, __uint_as_float(lb));
}

__device__ __forceinline__ void mma_tf32(float* c,
        uint32_t a0, uint32_t a1, uint32_t a2, uint32_t a3,
        uint32_t b0, uint32_t b1) {
    asm("mma.sync.aligned.m16n8k8.row.col.f32.tf32.tf32.f32 "
        "{%0,%1,%2,%3}, {%4,%5,%6,%7}, {%8,%9}, {%0,%1,%2,%3};"
        : "+f"(c[0]), "+f"(c[1]), "+f"(c[2]), "+f"(c[3])
        : "r"(a0), "r"(a1), "r"(a2), "r"(a3), "r"(b0), "r"(b1));
}

// 3xTF32 with pre-split float4 A (hi,lo) and float2 B (hi,lo)
__device__ __forceinline__ void mma3_f(float* c, float4 ah, float4 al,
                                       float2 bhv, float2 blv) {
    uint32_t a0 = __float_as_uint(ah.x), a1 = __float_as_uint(ah.y);
    uint32_t a2 = __float_as_uint(ah.z), a3 = __float_as_uint(ah.w);
    uint32_t l0 = __float_as_uint(al.x), l1 = __float_as_uint(al.y);
    uint32_t l2 = __float_as_uint(al.z), l3 = __float_as_uint(al.w);
    uint32_t b0 = __float_as_uint(bhv.x), b1 = __float_as_uint(bhv.y);
    uint32_t c0 = __float_as_uint(blv.x), c1 = __float_as_uint(blv.y);
    mma_tf32(c, a0, a1, a2, a3, b0, b1);
    mma_tf32(c, a0, a1, a2, a3, c0, c1);
    mma_tf32(c, l0, l1, l2, l3, b0, b1);
}

__device__ __forceinline__ void cp16(float* smem_dst, const float* gsrc) {
    uint32_t s = (uint32_t)__cvta_generic_to_shared(smem_dst);
    asm volatile("cp.async.ca.shared.global [%0], [%1], 16;" :: "r"(s), "l"(gsrc));
}
__device__ __forceinline__ void cp_commit() {
    asm volatile("cp.async.commit_group;");
}

// ============================================================
// Kernel 1: embed + pos + LayerNorm -> split tiled h planes
// ============================================================
#define EMB_SMEM (2 * 16 * 512 * 4)   // 64KB

__global__ void __launch_bounds__(256) embed_ln_kernel(
        const int* __restrict__ x_seq,
        const float* __restrict__ word_emb,
        const float* __restrict__ pos_emb,
        const float* __restrict__ ln_w,
        const float* __restrict__ ln_b) {
    extern __shared__ float es[];
    float* shi = es;
    float* slo = es + 8192;

    int rb   = blockIdx.x;
    int tid  = threadIdx.x;
    int w    = tid >> 5, lane = tid & 31;
    int rloc = 2 * w + (lane >> 4);
    int li   = lane & 15;
    int row  = rb * 16 + rloc;
    int s    = row & (SS - 1);
    int x    = x_seq[row];
    const float* we = word_emb + (size_t)x * DD;
    const float* pe = pos_emb  + (size_t)s * DD;

    float v[32];
    float sum = 0.f;
#pragma unroll
    for (int q = 0; q < 8; q++) {
        int c = li * 32 + q * 4;
        float4 a = *(const float4*)&we[c];
        float4 b = *(const float4*)&pe[c];
        v[q*4+0] = a.x + b.x; v[q*4+1] = a.y + b.y;
        v[q*4+2] = a.z + b.z; v[q*4+3] = a.w + b.w;
        sum += v[q*4+0] + v[q*4+1] + v[q*4+2] + v[q*4+3];
    }
#pragma unroll
    for (int o = 8; o > 0; o >>= 1) sum += __shfl_xor_sync(~0u, sum, o);
    float mu = sum * (1.0f / DD);
    float sq = 0.f;
#pragma unroll
    for (int q = 0; q < 32; q++) { float d = v[q] - mu; sq += d * d; }
#pragma unroll
    for (int o = 8; o > 0; o >>= 1) sq += __shfl_xor_sync(~0u, sq, o);
    float rstd = rsqrtf(sq * (1.0f / DD) + 1e-5f);

    int g  = rloc & 7, hh_ = rloc >> 3;
#pragma unroll
    for (int q = 0; q < 32; q++) {
        int c = li * 32 + q;
        float o = (v[q] - mu) * rstd * ln_w[c] + ln_b[c];
        float2 sp = tf32_split(o);
        int kb = c >> 3, tig = c & 3, ch = (c >> 2) & 1;
        int ta = (kb * 32 + g * 4 + tig) * 4 + hh_ + 2 * ch;
        shi[ta] = sp.x;
        slo[ta] = sp.y;
    }
    __syncthreads();
    size_t base = (size_t)rb * 8192;
#pragma unroll
    for (int r = 0; r < 8; r++) {
        int i = (tid + r * 256) * 4;
        *(float4*)&g_ah[base + i] = *(const float4*)&shi[i];
        *(float4*)&g_al[base + i] = *(const float4*)&slo[i];
    }
}

// ============================================================
// Kernel 1b: split+tile weights (one-shot)
// ============================================================
__global__ void split_w_kernel(const float* __restrict__ wq,
                               const float* __restrict__ wk,
                               const float* __restrict__ wv) {
    int idx = blockIdx.x * 256 + threadIdx.x;
    int z = idx >> 18;
    int rem = idx & ((1 << 18) - 1);
    int n = rem >> 9, k = rem & 511;
    const float* W = (z == 0) ? wq : (z == 1) ? wk : wv;
    float2 sp = tf32_split(W[(size_t)n * DD + k]);
    int cb = n >> 3, kb = k >> 3, g = n & 7, tig = k & 3, e = (k >> 2) & 1;
    size_t a = ((size_t)(cb * 64 + kb) * 32 + g * 4 + tig) * 2 + e;
    g_bh[z][a] = sp.x;
    g_bl[z][a] = sp.y;
}

// ============================================================
// Kernel 2: QKV GEMM (3xTF32 mma, cp.async) — epilogue scatters
// split fragment planes for Q (A-frag) / K,V (B-frag)
// ============================================================
#define QKV_SMEM (2 * 8192 * 4)   // 64KB

__global__ void __launch_bounds__(256) qkv_mma_kernel(
        const float* __restrict__ bq, const float* __restrict__ bk,
        const float* __restrict__ bv) {
    const float* bias;
    int z = blockIdx.z;
    bias = (z == 0) ? bq : (z == 1) ? bk : bv;
    const float* Bh = g_bh[z];
    const float* Bl = g_bl[z];

    extern __shared__ float smem[];
    int tid  = threadIdx.x;
    int warp = tid >> 5, lane = tid & 31;
    int wm = warp & 1, wn = warp >> 1;
    int rb0 = blockIdx.x * 8;
    int cb0 = blockIdx.y * 16;

    float acc[4][4][4] = {};

    auto copy_chunk = [&](float* st, int kc) {
#pragma unroll
        for (int r = 0; r < 2; r++) {
            int f = (tid + r * 256) * 4;
            int i = f >> 8, j = (f >> 7) & 1, t = f & 127;
            size_t src = ((size_t)(rb0 + i) * 64 + kc * 2 + j) * 128 + t;
            cp16(&st[f],        &g_ah[src]);
            cp16(&st[2048 + f], &g_al[src]);
        }
#pragma unroll
        for (int r = 0; r < 2; r++) {
            int f = (tid + r * 256) * 4;
            int i = f >> 7, j = (f >> 6) & 1, t = f & 63;
            size_t src = ((size_t)(cb0 + i) * 64 + kc * 2 + j) * 64 + t;
            cp16(&st[4096 + f], &Bh[src]);
            cp16(&st[6144 + f], &Bl[src]);
        }
    };

    copy_chunk(smem, 0);
    cp_commit();

    for (int kc = 0; kc < 32; kc++) {
        float* cur = smem + (kc & 1) * 8192;
        if (kc < 31) {
            copy_chunk(smem + ((kc + 1) & 1) * 8192, kc + 1);
            cp_commit();
            asm volatile("cp.async.wait_group 1;");
        } else {
            asm volatile("cp.async.wait_group 0;");
        }
        __syncthreads();

#pragma unroll
        for (int j = 0; j < 2; j++) {
            float2 bhf[4], blf[4];
#pragma unroll
            for (int nf = 0; nf < 4; nf++) {
                int bi = (((wn * 4 + nf) * 2 + j) * 32 + lane) * 2;
                bhf[nf] = *(const float2*)&cur[4096 + bi];
                blf[nf] = *(const float2*)&cur[6144 + bi];
            }
#pragma unroll
            for (int mf = 0; mf < 4; mf++) {
                int ai = (((wm * 4 + mf) * 2 + j) * 32 + lane) * 4;
                float4 ah = *(const float4*)&cur[ai];
                float4 al = *(const float4*)&cur[2048 + ai];
#pragma unroll
                for (int nf = 0; nf < 4; nf++)
                    mma3_f(acc[mf][nf], ah, al, bhf[nf], blf[nf]);
            }
        }
        __syncthreads();
    }

    // ---- epilogue: bias + split-scatter into fragment planes ----
    int gg = lane >> 2, tg = lane & 3;
    int row0 = blockIdx.x * 128, col0 = blockIdx.y * 128;
#pragma unroll
    for (int mf = 0; mf < 4; mf++) {
#pragma unroll
        for (int half = 0; half < 2; half++) {
            int t  = row0 + wm * 64 + mf * 16 + gg + half * 8;
            int b_ = t >> 9, s_ = t & 511;
#pragma unroll
            for (int nf = 0; nf < 4; nf++) {
#pragma unroll
                for (int c2 = 0; c2 < 2; c2++) {
                    int col = col0 + wn * 32 + nf * 8 + 2 * tg + c2;
                    int h_ = col >> 6, d = col & 63;
                    int bhx = b_ * HH + h_;
                    float val = acc[mf][nf][half * 2 + c2] + __ldg(&bias[col]);
                    float2 sp = tf32_split(val);
                    if (z == 0) {
                        size_t a = (((size_t)bhx * 32 + (s_ >> 4)) * 8 + (d >> 3)) * 128
                                 + ((s_ & 7) * 4 + (d & 3)) * 4
                                 + ((s_ >> 3) & 1) + 2 * ((d >> 2) & 1);
                        gQh[a] = sp.x; gQl[a] = sp.y;
                    } else if (z == 1) {
                        size_t a = (((size_t)bhx * 64 + (s_ >> 3)) * 8 + (d >> 3)) * 64
                                 + ((s_ & 7) * 4 + (d & 3)) * 2 + ((d >> 2) & 1);
                        gKh[a] = sp.x; gKl[a] = sp.y;
                    } else {
                        size_t a = (((size_t)bhx * 64 + (s_ >> 3)) * 8 + (d >> 3)) * 64
                                 + ((d & 7) * 4 + (s_ & 3)) * 2 + ((s_ >> 2) & 1);
                        gVh[a] = sp.x; gVl[a] = sp.y;
                    }
                }
            }
        }
    }
}

// ============================================================
// Kernel 3: attention — mma QK^T, exact softmax, mma PV
// CTA = (qtile 64, head, batch), 256 thr / 8 warps.
// smem: sc 64x516 | buf 2x8192 (K stages / probsA+V stages) | msm | rinv
// ============================================================
#define SCP 516
#define SC_FL (64 * SCP)          // 33024
#define STG_FL 8192
#define ATTN_SMEM ((SC_FL + 2 * STG_FL + 512 + 64) * 4)   // 199936 B

__global__ void __launch_bounds__(256, 1) attn_kernel(const int* __restrict__ mask,
                                                      float* __restrict__ out) {
    int qt = blockIdx.x, hh = blockIdx.y, bb = blockIdx.z;
    extern __shared__ float sm[];
    float* sc   = sm;                 // score strip 64 x 516
    float* buf  = sm + SC_FL;         // 2 stages x 8192
    float* msm  = buf + 2 * STG_FL;   // 512 (pre-scaled mask)
    float* rinv = msm + 512;          // 64

    int tid  = threadIdx.x;
    int warp = tid >> 5, lane = tid & 31;
    int g = lane >> 2, tig = lane & 3;
    int wq = warp >> 1, wk = warp & 1;   // wq: m-frag group; wk: n-half
    int bh = bb * HH + hh;

    for (int i = tid; i < SS; i += 256)
        msm[i] = (1.0f - (float)mask[(size_t)bb * SS + i]) * -1250.0f;  // -1e4/8

    // Q fragments -> registers (A-frag layout)
    float4 qfh[8], qfl[8];
    {
        size_t qb = (((size_t)bh * 32 + qt * 4 + wq) * 8) * 128 + lane * 4;
#pragma unroll
        for (int kf = 0; kf < 8; kf++) {
            qfh[kf] = *(const float4*)&gQh[qb + kf * 128];
            qfl[kf] = *(const float4*)&gQl[qb + kf * 128];
        }
    }

    // ---- phase 1: QK^T over 8 chunks of 64 keys ----
    size_t kcb = (size_t)bh * 32768;   // 64nf*8kf*64
    auto copyK = [&](int st, int ch) {
        const float* sH = gKh + kcb + (size_t)ch * 4096;
        const float* sL = gKl + kcb + (size_t)ch * 4096;
        float* d = buf + st * STG_FL;
#pragma unroll
        for (int r = 0; r < 4; r++) {
            int off = (tid + r * 256) * 4;
            cp16(&d[off],        &sH[off]);
            cp16(&d[4096 + off], &sL[off]);
        }
    };
    copyK(0, 0); cp_commit();
    for (int ch = 0; ch < 8; ch++) {
        float* cur = buf + (ch & 1) * STG_FL;
        if (ch < 7) { copyK((ch + 1) & 1, ch + 1); cp_commit();
                      asm volatile("cp.async.wait_group 1;"); }
        else        { asm volatile("cp.async.wait_group 0;"); }
        __syncthreads();
        float acc[4][4] = {};
#pragma unroll
        for (int nf = 0; nf < 4; nf++) {
            int nl = wk * 4 + nf;
#pragma unroll
            for (int kf = 0; kf < 8; kf++) {
                float2 b2h = *(const float2*)&cur[((nl * 8 + kf) * 32 + lane) * 2];
                float2 b2l = *(const float2*)&cur[4096 + ((nl * 8 + kf) * 32 + lane) * 2];
                mma3_f(acc[nf], qfh[kf], qfl[kf], b2h, b2l);
            }
        }
#pragma unroll
        for (int nf = 0; nf < 4; nf++) {
            int key = ch * 64 + wk * 32 + nf * 8 + 2 * tig;
            float2 m2 = *(const float2*)&msm[key];
            int q0 = wq * 16 + g;
            *(float2*)&sc[q0 * SCP + key] =
                make_float2(acc[nf][0] * m2.x, acc[nf][1] * m2.y);
            *(float2*)&sc[(q0 + 8) * SCP + key] =
                make_float2(acc[nf][2] * m2.x, acc[nf][3] * m2.y);
        }
        __syncthreads();
    }

    // ---- phase 2: softmax (unnormalized exps kept; 1/sum saved) ----
    {
        int r = tid >> 2, l4 = tid & 3;
        float mx = -INFINITY;
        for (int c = l4 * 4; c < SS; c += 16) {
            float4 s4 = *(const float4*)&sc[r * SCP + c];
            mx = fmaxf(mx, fmaxf(fmaxf(s4.x, s4.y), fmaxf(s4.z, s4.w)));
        }
        mx = fmaxf(mx, __shfl_xor_sync(~0u, mx, 1));
        mx = fmaxf(mx, __shfl_xor_sync(~0u, mx, 2));
        float sum = 0.f;
        for (int c = l4 * 4; c < SS; c += 16) {
            float4 s4 = *(const float4*)&sc[r * SCP + c];
            s4.x = __expf(s4.x - mx); s4.y = __expf(s4.y - mx);
            s4.z = __expf(s4.z - mx); s4.w = __expf(s4.w - mx);
            *(float4*)&sc[r * SCP + c] = s4;
            sum += s4.x + s4.y + s4.z + s4.w;
        }
        sum += __shfl_xor_sync(~0u, sum, 1);
        sum += __shfl_xor_sync(~0u, sum, 2);
        if (l4 == 0) rinv[r] = 1.0f / sum;
    }
    __syncthreads();

    // ---- phase 3: write normalized probs (coalesced) ----
    {
        float* pbase = out + OUT_PROBS + ((size_t)bh * SS + (size_t)qt * 64) * SS;
#pragma unroll
        for (int t = 0; t < 32; t++) {
            int idx = tid + t * 256;
            int r = idx >> 7, c = (idx & 127) * 4;
            float rv = rinv[r];
            float4 e4 = *(const float4*)&sc[r * SCP + c];
            *(float4*)&pbase[(size_t)r * SS + c] =
                make_float4(e4.x * rv, e4.y * rv, e4.z * rv, e4.w * rv);
        }
    }

    // ---- phase 4: PV over 16 chunks of 32 keys (double-buffered) ----
    size_t vcb = (size_t)bh * 32768;
    auto prepPV = [&](int st, int ch) {
        float* d = buf + st * STG_FL;
        const float* sH = gVh + vcb + (size_t)ch * 2048;
        const float* sL = gVl + vcb + (size_t)ch * 2048;
#pragma unroll
        for (int r = 0; r < 2; r++) {
            int off = (tid + r * 256) * 4;
            cp16(&d[4096 + off], &sH[off]);
            cp16(&d[6144 + off], &sL[off]);
        }
        // gather-split probs -> A-frag layout [qf4][kf4][lane][e4]
#pragma unroll
        for (int sx = 0; sx < 2; sx++) {
            int slot = tid * 2 + sx;           // 0..511
            int sl = slot & 31;
            int kf = (slot >> 5) & 3;
            int qf = slot >> 7;
            int sg = sl >> 2, stg = sl & 3;
            int q0 = qf * 16 + sg;
            int k0 = ch * 32 + kf * 8 + stg;
            float rv0 = rinv[q0], rv1 = rinv[q0 + 8];
            float2 s0 = tf32_split(sc[q0 * SCP + k0] * rv0);
            float2 s1 = tf32_split(sc[(q0 + 8) * SCP + k0] * rv1);
            float2 s2 = tf32_split(sc[q0 * SCP + k0 + 4] * rv0);
            float2 s3 = tf32_split(sc[(q0 + 8) * SCP + k0 + 4] * rv1);
            *(float4*)&d[slot * 4]        = make_float4(s0.x, s1.x, s2.x, s3.x);
            *(float4*)&d[2048 + slot * 4] = make_float4(s0.y, s1.y, s2.y, s3.y);
        }
    };

    float acc2[4][4] = {};
    prepPV(0, 0); cp_commit();
    for (int ch = 0; ch < 16; ch++) {
        float* cur = buf + (ch & 1) * STG_FL;
        if (ch < 15) { prepPV((ch + 1) & 1, ch + 1); cp_commit();
                       asm volatile("cp.async.wait_group 1;"); }
        else         { asm volatile("cp.async.wait_group 0;"); }
        __syncthreads();
#pragma unroll
        for (int kf = 0; kf < 4; kf++) {
            float4 ah = *(const float4*)&cur[((wq * 4 + kf) * 32 + lane) * 4];
            float4 al = *(const float4*)&cur[2048 + ((wq * 4 + kf) * 32 + lane) * 4];
#pragma unroll
            for (int nf = 0; nf < 4; nf++) {
                int ng = wk * 4 + nf;
                float2 b2h = *(const float2*)&cur[4096 + ((kf * 8 + ng) * 32 + lane) * 2];
                float2 b2l = *(const float2*)&cur[6144 + ((kf * 8 + ng) * 32 + lane) * 2];
                mma3_f(acc2[nf], ah, al, b2h, b2l);
            }
        }
        __syncthreads();
    }

    // ---- epilogue: ctx (+ ctx0) ----
    int q0 = qt * 64 + wq * 16 + g;
#pragma unroll
    for (int nf = 0; nf < 4; nf++) {
        int dcol = hh * 64 + wk * 32 + nf * 8 + 2 * tig;
        size_t o0 = OUT_CTX + ((size_t)bb * SS + q0) * DD + dcol;
        size_t o1 = OUT_CTX + ((size_t)bb * SS + q0 + 8) * DD + dcol;
        *(float2*)&out[o0] = make_float2(acc2[nf][0], acc2[nf][1]);
        *(float2*)&out[o1] = make_float2(acc2[nf][2], acc2[nf][3]);
        if (q0 == 0)
            *(float2*)&out[(size_t)bb * DD + dcol] =
                make_float2(acc2[nf][0], acc2[nf][1]);
    }
}

// ============================================================
extern "C" void kernel_launch(void* const* d_in, const int* in_sizes, int n_in,
                              void* d_out, int out_size) {
    const int*   x_seq    = (const int*)  d_in[0];
    const int*   mask     = (const int*)  d_in[1];
    const float* word_emb = (const float*)d_in[2];
    const float* pos_emb  = (const float*)d_in[3];
    const float* ln_w     = (const float*)d_in[4];
    const float* ln_b     = (const float*)d_in[5];
    const float* wq       = (const float*)d_in[6];
    const float* bq       = (const float*)d_in[7];
    const float* wk       = (const float*)d_in[8];
    const float* bk       = (const float*)d_in[9];
    const float* wv       = (const float*)d_in[10];
    const float* bv       = (const float*)d_in[11];
    float* out = (float*)d_out;

    cudaFuncSetAttribute(embed_ln_kernel, cudaFuncAttributeMaxDynamicSharedMemorySize,
                         EMB_SMEM);
    embed_ln_kernel<<<TT / 16, 256, EMB_SMEM>>>(x_seq, word_emb, pos_emb, ln_w, ln_b);

    split_w_kernel<<<3 * 512 * 512 / 256, 256>>>(wq, wk, wv);

    cudaFuncSetAttribute(qkv_mma_kernel, cudaFuncAttributeMaxDynamicSharedMemorySize,
                         QKV_SMEM);
    dim3 ggrid(TT / 128, DD / 128, 3);
    qkv_mma_kernel<<<ggrid, 256, QKV_SMEM>>>(bq, bk, bv);

    cudaFuncSetAttribute(attn_kernel, cudaFuncAttributeMaxDynamicSharedMemorySize,
                         ATTN_SMEM);
    dim3 agrid(SS / 64, HH, BB);
    attn_kernel<<<agrid, 256, ATTN_SMEM>>>(mask, out);
}

// round 9
// speedup vs baseline: 1.5178x; 1.0470x over previous
#include <cuda_runtime.h>
#include <math.h>
#include <stdint.h>

#define BB 32
#define SS 512
#define DD 512
#define HH 8
#define DHH 64
#define TT (BB*SS)   // 16384 tokens
#define NBH (BB*HH)  // 256

// ---- scratch (__device__ globals; no dynamic alloc) ----
__device__ float g_ah[(size_t)1024 * 64 * 128];
__device__ float g_al[(size_t)1024 * 64 * 128];
__device__ float g_bh[3][(size_t)64 * 64 * 64];
__device__ float g_bl[3][(size_t)64 * 64 * 64];
// Q split A-frag planes: [bh(256)][qf(32)][kf(8)][lane(32)][e(4)]
__device__ float gQh[(size_t)NBH * 32 * 8 * 128];
__device__ float gQl[(size_t)NBH * 32 * 8 * 128];
// K split B-frag planes (n = key): [bh][nf(64)][kf(8)][lane(32)][e(2)]
__device__ float gKh[(size_t)NBH * 64 * 8 * 64];
__device__ float gKl[(size_t)NBH * 64 * 8 * 64];
// V split B-frag planes (n = dh, k = key): [bh][kf(64)][nf(8)][lane(32)][e(2)]
__device__ float gVh[(size_t)NBH * 64 * 8 * 64];
__device__ float gVl[(size_t)NBH * 64 * 8 * 64];

// output layout: [ ctx0: B*D ][ ctx: B*S*D ][ probs: B*H*S*S ]
#define OUT_CTX   ((size_t)BB * DD)
#define OUT_PROBS (OUT_CTX + (size_t)BB * SS * DD)

// ============================================================
// tf32 split + mma helpers
// ============================================================
__device__ __forceinline__ float2 tf32_split(float x) {
    uint32_t hb;
    asm("cvt.rna.tf32.f32 %0, %1;" : "=r"(hb) : "f"(x));
    float hf = __uint_as_float(hb);
    float lo = x - hf;
    uint32_t lb;
    asm("cvt.rna.tf32.f32 %0, %1;" : "=r"(lb) : "f"(lo));
    return make_float2(hf, __uint_as_float(lb));
}

__device__ __forceinline__ void mma_tf32(float* c,
        uint32_t a0, uint32_t a1, uint32_t a2, uint32_t a3,
        uint32_t b0, uint32_t b1) {
    asm("mma.sync.aligned.m16n8k8.row.col.f32.tf32.tf32.f32 "
        "{%0,%1,%2,%3}, {%4,%5,%6,%7}, {%8,%9}, {%0,%1,%2,%3};"
        : "+f"(c[0]), "+f"(c[1]), "+f"(c[2]), "+f"(c[3])
        : "r"(a0), "r"(a1), "r"(a2), "r"(a3), "r"(b0), "r"(b1));
}

__device__ __forceinline__ void mma3_f(float* c, float4 ah, float4 al,
                                       float2 bhv, float2 blv) {
    uint32_t a0 = __float_as_uint(ah.x), a1 = __float_as_uint(ah.y);
    uint32_t a2 = __float_as_uint(ah.z), a3 = __float_as_uint(ah.w);
    uint32_t l0 = __float_as_uint(al.x), l1 = __float_as_uint(al.y);
    uint32_t l2 = __float_as_uint(al.z), l3 = __float_as_uint(al.w);
    uint32_t b0 = __float_as_uint(bhv.x), b1 = __float_as_uint(bhv.y);
    uint32_t c0 = __float_as_uint(blv.x), c1 = __float_as_uint(blv.y);
    mma_tf32(c, a0, a1, a2, a3, b0, b1);
    mma_tf32(c, a0, a1, a2, a3, c0, c1);
    mma_tf32(c, l0, l1, l2, l3, b0, b1);
}

__device__ __forceinline__ void cp16(float* smem_dst, const float* gsrc) {
    uint32_t s = (uint32_t)__cvta_generic_to_shared(smem_dst);
    asm volatile("cp.async.ca.shared.global [%0], [%1], 16;" :: "r"(s), "l"(gsrc));
}
__device__ __forceinline__ void cp_commit() {
    asm volatile("cp.async.commit_group;");
}

// ============================================================
// Kernel 1: embed + pos + LayerNorm -> split tiled h planes
// ============================================================
#define EMB_SMEM (2 * 16 * 512 * 4)

__global__ void __launch_bounds__(256) embed_ln_kernel(
        const int* __restrict__ x_seq,
        const float* __restrict__ word_emb,
        const float* __restrict__ pos_emb,
        const float* __restrict__ ln_w,
        const float* __restrict__ ln_b) {
    extern __shared__ float es[];
    float* shi = es;
    float* slo = es + 8192;

    int rb   = blockIdx.x;
    int tid  = threadIdx.x;
    int w    = tid >> 5, lane = tid & 31;
    int rloc = 2 * w + (lane >> 4);
    int li   = lane & 15;
    int row  = rb * 16 + rloc;
    int s    = row & (SS - 1);
    int x    = x_seq[row];
    const float* we = word_emb + (size_t)x * DD;
    const float* pe = pos_emb  + (size_t)s * DD;

    float v[32];
    float sum = 0.f;
#pragma unroll
    for (int q = 0; q < 8; q++) {
        int c = li * 32 + q * 4;
        float4 a = *(const float4*)&we[c];
        float4 b = *(const float4*)&pe[c];
        v[q*4+0] = a.x + b.x; v[q*4+1] = a.y + b.y;
        v[q*4+2] = a.z + b.z; v[q*4+3] = a.w + b.w;
        sum += v[q*4+0] + v[q*4+1] + v[q*4+2] + v[q*4+3];
    }
#pragma unroll
    for (int o = 8; o > 0; o >>= 1) sum += __shfl_xor_sync(~0u, sum, o);
    float mu = sum * (1.0f / DD);
    float sq = 0.f;
#pragma unroll
    for (int q = 0; q < 32; q++) { float d = v[q] - mu; sq += d * d; }
#pragma unroll
    for (int o = 8; o > 0; o >>= 1) sq += __shfl_xor_sync(~0u, sq, o);
    float rstd = rsqrtf(sq * (1.0f / DD) + 1e-5f);

    int g  = rloc & 7, hh_ = rloc >> 3;
#pragma unroll
    for (int q = 0; q < 32; q++) {
        int c = li * 32 + q;
        float o = (v[q] - mu) * rstd * ln_w[c] + ln_b[c];
        float2 sp = tf32_split(o);
        int kb = c >> 3, tig = c & 3, ch = (c >> 2) & 1;
        int ta = (kb * 32 + g * 4 + tig) * 4 + hh_ + 2 * ch;
        shi[ta] = sp.x;
        slo[ta] = sp.y;
    }
    __syncthreads();
    size_t base = (size_t)rb * 8192;
#pragma unroll
    for (int r = 0; r < 8; r++) {
        int i = (tid + r * 256) * 4;
        *(float4*)&g_ah[base + i] = *(const float4*)&shi[i];
        *(float4*)&g_al[base + i] = *(const float4*)&slo[i];
    }
}

// ============================================================
// Kernel 1b: split+tile weights (one-shot)
// ============================================================
__global__ void split_w_kernel(const float* __restrict__ wq,
                               const float* __restrict__ wk,
                               const float* __restrict__ wv) {
    int idx = blockIdx.x * 256 + threadIdx.x;
    int z = idx >> 18;
    int rem = idx & ((1 << 18) - 1);
    int n = rem >> 9, k = rem & 511;
    const float* W = (z == 0) ? wq : (z == 1) ? wk : wv;
    float2 sp = tf32_split(W[(size_t)n * DD + k]);
    int cb = n >> 3, kb = k >> 3, g = n & 7, tig = k & 3, e = (k >> 2) & 1;
    size_t a = ((size_t)(cb * 64 + kb) * 32 + g * 4 + tig) * 2 + e;
    g_bh[z][a] = sp.x;
    g_bl[z][a] = sp.y;
}

// ============================================================
// Kernel 2: QKV GEMM (3xTF32 mma, cp.async) -> split frag planes
// ============================================================
#define QKV_SMEM (2 * 8192 * 4)

__global__ void __launch_bounds__(256, 2) qkv_mma_kernel(
        const float* __restrict__ bq, const float* __restrict__ bk,
        const float* __restrict__ bv) {
    const float* bias;
    int z = blockIdx.z;
    bias = (z == 0) ? bq : (z == 1) ? bk : bv;
    const float* Bh = g_bh[z];
    const float* Bl = g_bl[z];

    extern __shared__ float smem[];
    int tid  = threadIdx.x;
    int warp = tid >> 5, lane = tid & 31;
    int wm = warp & 1, wn = warp >> 1;
    int rb0 = blockIdx.x * 8;
    int cb0 = blockIdx.y * 16;

    float acc[4][4][4] = {};

    auto copy_chunk = [&](float* st, int kc) {
#pragma unroll
        for (int r = 0; r < 2; r++) {
            int f = (tid + r * 256) * 4;
            int i = f >> 8, j = (f >> 7) & 1, t = f & 127;
            size_t src = ((size_t)(rb0 + i) * 64 + kc * 2 + j) * 128 + t;
            cp16(&st[f],        &g_ah[src]);
            cp16(&st[2048 + f], &g_al[src]);
        }
#pragma unroll
        for (int r = 0; r < 2; r++) {
            int f = (tid + r * 256) * 4;
            int i = f >> 7, j = (f >> 6) & 1, t = f & 63;
            size_t src = ((size_t)(cb0 + i) * 64 + kc * 2 + j) * 64 + t;
            cp16(&st[4096 + f], &Bh[src]);
            cp16(&st[6144 + f], &Bl[src]);
        }
    };

    copy_chunk(smem, 0);
    cp_commit();

    for (int kc = 0; kc < 32; kc++) {
        float* cur = smem + (kc & 1) * 8192;
        if (kc < 31) {
            copy_chunk(smem + ((kc + 1) & 1) * 8192, kc + 1);
            cp_commit();
            asm volatile("cp.async.wait_group 1;");
        } else {
            asm volatile("cp.async.wait_group 0;");
        }
        __syncthreads();

#pragma unroll
        for (int j = 0; j < 2; j++) {
            float2 bhf[4], blf[4];
#pragma unroll
            for (int nf = 0; nf < 4; nf++) {
                int bi = (((wn * 4 + nf) * 2 + j) * 32 + lane) * 2;
                bhf[nf] = *(const float2*)&cur[4096 + bi];
                blf[nf] = *(const float2*)&cur[6144 + bi];
            }
#pragma unroll
            for (int mf = 0; mf < 4; mf++) {
                int ai = (((wm * 4 + mf) * 2 + j) * 32 + lane) * 4;
                float4 ah = *(const float4*)&cur[ai];
                float4 al = *(const float4*)&cur[2048 + ai];
#pragma unroll
                for (int nf = 0; nf < 4; nf++)
                    mma3_f(acc[mf][nf], ah, al, bhf[nf], blf[nf]);
            }
        }
        __syncthreads();
    }

    // ---- epilogue: bias + split-scatter into fragment planes ----
    int gg = lane >> 2, tg = lane & 3;
    int row0 = blockIdx.x * 128, col0 = blockIdx.y * 128;
#pragma unroll
    for (int mf = 0; mf < 4; mf++) {
#pragma unroll
        for (int half = 0; half < 2; half++) {
            int t  = row0 + wm * 64 + mf * 16 + gg + half * 8;
            int b_ = t >> 9, s_ = t & 511;
#pragma unroll
            for (int nf = 0; nf < 4; nf++) {
#pragma unroll
                for (int c2 = 0; c2 < 2; c2++) {
                    int col = col0 + wn * 32 + nf * 8 + 2 * tg + c2;
                    int h_ = col >> 6, d = col & 63;
                    int bhx = b_ * HH + h_;
                    float val = acc[mf][nf][half * 2 + c2] + __ldg(&bias[col]);
                    float2 sp = tf32_split(val);
                    if (z == 0) {
                        size_t a = (((size_t)bhx * 32 + (s_ >> 4)) * 8 + (d >> 3)) * 128
                                 + ((s_ & 7) * 4 + (d & 3)) * 4
                                 + ((s_ >> 3) & 1) + 2 * ((d >> 2) & 1);
                        gQh[a] = sp.x; gQl[a] = sp.y;
                    } else if (z == 1) {
                        size_t a = (((size_t)bhx * 64 + (s_ >> 3)) * 8 + (d >> 3)) * 64
                                 + ((s_ & 7) * 4 + (d & 3)) * 2 + ((d >> 2) & 1);
                        gKh[a] = sp.x; gKl[a] = sp.y;
                    } else {
                        size_t a = (((size_t)bhx * 64 + (s_ >> 3)) * 8 + (d >> 3)) * 64
                                 + ((d & 7) * 4 + (s_ & 3)) * 2 + ((s_ >> 2) & 1);
                        gVh[a] = sp.x; gVl[a] = sp.y;
                    }
                }
            }
        }
    }
}

// ============================================================
// Kernel 3: attention — score strip lives in the probs OUTPUT
// region (gmem); smem only holds cp.async staging -> 2 CTAs/SM.
// ============================================================
#define STG_FL 8192
#define ATTN_SMEM ((2 * STG_FL + 512) * 4)   // 67.6 KB

__global__ void __launch_bounds__(256, 2) attn_kernel(const int* __restrict__ mask,
                                                      float* __restrict__ out) {
    int qt = blockIdx.x, hh = blockIdx.y, bb = blockIdx.z;
    extern __shared__ float sm[];
    float* buf  = sm;                 // 2 stages x 8192
    float* msm  = sm + 2 * STG_FL;    // 512 (pre-scaled mask)

    int tid  = threadIdx.x;
    int warp = tid >> 5, lane = tid & 31;
    int g = lane >> 2, tig = lane & 3;
    int wq = warp >> 1, wk = warp & 1;
    int bh = bb * HH + hh;
    // this CTA's 64 x 512 strip inside the probs output
    float* ps = out + OUT_PROBS + ((size_t)bh * SS + (size_t)qt * 64) * SS;

    for (int i = tid; i < SS; i += 256)
        msm[i] = (1.0f - (float)mask[(size_t)bb * SS + i]) * -1250.0f;  // -1e4/8

    // Q fragments -> registers (A-frag layout)
    float4 qfh[8], qfl[8];
    {
        size_t qb = (((size_t)bh * 32 + qt * 4 + wq) * 8) * 128 + lane * 4;
#pragma unroll
        for (int kf = 0; kf < 8; kf++) {
            qfh[kf] = *(const float4*)&gQh[qb + kf * 128];
            qfl[kf] = *(const float4*)&gQl[qb + kf * 128];
        }
    }

    // ---- phase 1: QK^T -> masked scores into ps ----
    size_t kcb = (size_t)bh * 32768;
    auto copyK = [&](int st, int ch) {
        const float* sH = gKh + kcb + (size_t)ch * 4096;
        const float* sL = gKl + kcb + (size_t)ch * 4096;
        float* d = buf + st * STG_FL;
#pragma unroll
        for (int r = 0; r < 4; r++) {
            int off = (tid + r * 256) * 4;
            cp16(&d[off],        &sH[off]);
            cp16(&d[4096 + off], &sL[off]);
        }
    };
    copyK(0, 0); cp_commit();
    for (int ch = 0; ch < 8; ch++) {
        float* cur = buf + (ch & 1) * STG_FL;
        if (ch < 7) { copyK((ch + 1) & 1, ch + 1); cp_commit();
                      asm volatile("cp.async.wait_group 1;"); }
        else        { asm volatile("cp.async.wait_group 0;"); }
        __syncthreads();
        float acc[4][4] = {};
#pragma unroll
        for (int nf = 0; nf < 4; nf++) {
            int nl = wk * 4 + nf;
#pragma unroll
            for (int kf = 0; kf < 8; kf++) {
                float2 b2h = *(const float2*)&cur[((nl * 8 + kf) * 32 + lane) * 2];
                float2 b2l = *(const float2*)&cur[4096 + ((nl * 8 + kf) * 32 + lane) * 2];
                mma3_f(acc[nf], qfh[kf], qfl[kf], b2h, b2l);
            }
        }
#pragma unroll
        for (int nf = 0; nf < 4; nf++) {
            int key = ch * 64 + wk * 32 + nf * 8 + 2 * tig;
            float2 m2 = *(const float2*)&msm[key];
            int q0 = wq * 16 + g;
            *(float2*)&ps[(size_t)q0 * SS + key] =
                make_float2(acc[nf][0] * m2.x, acc[nf][1] * m2.y);
            *(float2*)&ps[(size_t)(q0 + 8) * SS + key] =
                make_float2(acc[nf][2] * m2.x, acc[nf][3] * m2.y);
        }
        __syncthreads();
    }

    // ---- phase 2: softmax in-place in ps (streaming, FULL 512 cols) ----
    {
        int r = tid >> 2, l4 = tid & 3;
        float* row = ps + (size_t)r * SS;
        float mx = -INFINITY;
        for (int c = l4 * 4; c < SS; c += 16) {
            float4 s4 = *(const float4*)&row[c];
            mx = fmaxf(mx, fmaxf(fmaxf(s4.x, s4.y), fmaxf(s4.z, s4.w)));
        }
        mx = fmaxf(mx, __shfl_xor_sync(~0u, mx, 1));
        mx = fmaxf(mx, __shfl_xor_sync(~0u, mx, 2));
        float sum = 0.f;
        for (int c = l4 * 4; c < SS; c += 16) {
            float4 s4 = *(const float4*)&row[c];
            s4.x = __expf(s4.x - mx); s4.y = __expf(s4.y - mx);
            s4.z = __expf(s4.z - mx); s4.w = __expf(s4.w - mx);
            *(float4*)&row[c] = s4;
            sum += s4.x + s4.y + s4.z + s4.w;
        }
        sum += __shfl_xor_sync(~0u, sum, 1);
        sum += __shfl_xor_sync(~0u, sum, 2);
        float rv = 1.0f / sum;
        for (int c = l4 * 4; c < SS; c += 16) {
            float4 s4 = *(const float4*)&row[c];
            *(float4*)&row[c] =
                make_float4(s4.x * rv, s4.y * rv, s4.z * rv, s4.w * rv);
        }
    }
    __syncthreads();

    // ---- phase 3: PV over 16 chunks of 32 keys ----
    size_t vcb = (size_t)bh * 32768;
    auto prepPV = [&](int st, int ch) {
        float* d = buf + st * STG_FL;
        const float* sH = gVh + vcb + (size_t)ch * 2048;
        const float* sL = gVl + vcb + (size_t)ch * 2048;
#pragma unroll
        for (int r = 0; r < 2; r++) {
            int off = (tid + r * 256) * 4;
            cp16(&d[4096 + off], &sH[off]);
            cp16(&d[6144 + off], &sL[off]);
        }
#pragma unroll
        for (int sx = 0; sx < 2; sx++) {
            int slot = tid * 2 + sx;
            int sl = slot & 31;
            int kf = (slot >> 5) & 3;
            int qf = slot >> 7;
            int sg = sl >> 2, stg = sl & 3;
            int q0 = qf * 16 + sg;
            int k0 = ch * 32 + kf * 8 + stg;
            float2 s0 = tf32_split(ps[(size_t)q0 * SS + k0]);
            float2 s1 = tf32_split(ps[(size_t)(q0 + 8) * SS + k0]);
            float2 s2 = tf32_split(ps[(size_t)q0 * SS + k0 + 4]);
            float2 s3 = tf32_split(ps[(size_t)(q0 + 8) * SS + k0 + 4]);
            *(float4*)&d[slot * 4]        = make_float4(s0.x, s1.x, s2.x, s3.x);
            *(float4*)&d[2048 + slot * 4] = make_float4(s0.y, s1.y, s2.y, s3.y);
        }
    };

    float acc2[4][4] = {};
    prepPV(0, 0); cp_commit();
    for (int ch = 0; ch < 16; ch++) {
        float* cur = buf + (ch & 1) * STG_FL;
        if (ch < 15) { prepPV((ch + 1) & 1, ch + 1); cp_commit();
                       asm volatile("cp.async.wait_group 1;"); }
        else         { asm volatile("cp.async.wait_group 0;"); }
        __syncthreads();
#pragma unroll
        for (int kf = 0; kf < 4; kf++) {
            float4 ah = *(const float4*)&cur[((wq * 4 + kf) * 32 + lane) * 4];
            float4 al = *(const float4*)&cur[2048 + ((wq * 4 + kf) * 32 + lane) * 4];
#pragma unroll
            for (int nf = 0; nf < 4; nf++) {
                int ng = wk * 4 + nf;
                float2 b2h = *(const float2*)&cur[4096 + ((kf * 8 + ng) * 32 + lane) * 2];
                float2 b2l = *(const float2*)&cur[6144 + ((kf * 8 + ng) * 32 + lane) * 2];
                mma3_f(acc2[nf], ah, al, b2h, b2l);
            }
        }
        __syncthreads();
    }

    // ---- epilogue: ctx (+ ctx0) ----
    int q0 = qt * 64 + wq * 16 + g;
#pragma unroll
    for (int nf = 0; nf < 4; nf++) {
        int dcol = hh * 64 + wk * 32 + nf * 8 + 2 * tig;
        size_t o0 = OUT_CTX + ((size_t)bb * SS + q0) * DD + dcol;
        size_t o1 = OUT_CTX + ((size_t)bb * SS + q0 + 8) * DD + dcol;
        *(float2*)&out[o0] = make_float2(acc2[nf][0], acc2[nf][1]);
        *(float2*)&out[o1] = make_float2(acc2[nf][2], acc2[nf][3]);
        if (q0 == 0)
            *(float2*)&out[(size_t)bb * DD + dcol] =
                make_float2(acc2[nf][0], acc2[nf][1]);
    }
}

// ============================================================
extern "C" void kernel_launch(void* const* d_in, const int* in_sizes, int n_in,
                              void* d_out, int out_size) {
    const int*   x_seq    = (const int*)  d_in[0];
    const int*   mask     = (const int*)  d_in[1];
    const float* word_emb = (const float*)d_in[2];
    const float* pos_emb  = (const float*)d_in[3];
    const float* ln_w     = (const float*)d_in[4];
    const float* ln_b     = (const float*)d_in[5];
    const float* wq       = (const float*)d_in[6];
    const float* bq       = (const float*)d_in[7];
    const float* wk       = (const float*)d_in[8];
    const float* bk       = (const float*)d_in[9];
    const float* wv       = (const float*)d_in[10];
    const float* bv       = (const float*)d_in[11];
    float* out = (float*)d_out;

    cudaFuncSetAttribute(embed_ln_kernel, cudaFuncAttributeMaxDynamicSharedMemorySize,
                         EMB_SMEM);
    embed_ln_kernel<<<TT / 16, 256, EMB_SMEM>>>(x_seq, word_emb, pos_emb, ln_w, ln_b);

    split_w_kernel<<<3 * 512 * 512 / 256, 256>>>(wq, wk, wv);

    cudaFuncSetAttribute(qkv_mma_kernel, cudaFuncAttributeMaxDynamicSharedMemorySize,
                         QKV_SMEM);
    dim3 ggrid(TT / 128, DD / 128, 3);
    qkv_mma_kernel<<<ggrid, 256, QKV_SMEM>>>(bq, bk, bv);

    cudaFuncSetAttribute(attn_kernel, cudaFuncAttributeMaxDynamicSharedMemorySize,
                         ATTN_SMEM);
    dim3 agrid(SS / 64, HH, BB);
    attn_kernel<<<agrid, 256, ATTN_SMEM>>>(mask, out);
}